// round 4
// baseline (speedup 1.0000x reference)
#include <cuda_runtime.h>
#include <cuda_bf16.h>
#include <math.h>
#include <stdint.h>

#define NN 40000
#define NE 640000
#define DIM 128
#define NH 8
#define DH 16

// ---------------- scratch (device globals: allocation-free) ----------------
__device__ float g_Qh[(size_t)NN * DIM];
__device__ float g_Kh[(size_t)NN * DIM];
__device__ float g_Vh[(size_t)NN * DIM];
__device__ float g_Ee[(size_t)NE * 2 * DIM];
__device__ float g_et[(size_t)NE * DIM];
__device__ float g_lg[(size_t)NE * NH];
__device__ float g_mx[(size_t)NN * NH];
__device__ float g_den[(size_t)NN * NH];
__device__ float g_wV[(size_t)NN * DIM];
__device__ float g_rowV[(size_t)NN * DIM];
__device__ float g_hatt[(size_t)NN * DIM];
__device__ float g_v1[(size_t)NN * DIM];
__device__ float g_hbn[(size_t)NN * DIM];
__device__ float g_h2a[(size_t)NN * 2 * DIM];
__device__ float g_v2[(size_t)NN * DIM];
__device__ float g_s1[2 * DIM];
__device__ float g_s2[2 * DIM];
__device__ float g_se[2 * DIM];

static inline int cdiv(long long a, long long b) { return (int)((a + b - 1) / b); }

// ---------------- mma helpers ----------------
__device__ __forceinline__ uint32_t smem_u32(const void* p) {
    uint32_t a;
    asm("{ .reg .u64 t; cvta.to.shared.u64 t, %1; cvt.u32.u64 %0, t; }" : "=r"(a) : "l"(p));
    return a;
}
__device__ __forceinline__ void ldsm4(uint32_t (&r)[4], uint32_t addr) {
    asm volatile("ldmatrix.sync.aligned.m8n8.x4.shared.b16 {%0,%1,%2,%3}, [%4];"
                 : "=r"(r[0]), "=r"(r[1]), "=r"(r[2]), "=r"(r[3]) : "r"(addr));
}
__device__ __forceinline__ void ldsm4t(uint32_t (&r)[4], uint32_t addr) {
    asm volatile("ldmatrix.sync.aligned.m8n8.x4.trans.shared.b16 {%0,%1,%2,%3}, [%4];"
                 : "=r"(r[0]), "=r"(r[1]), "=r"(r[2]), "=r"(r[3]) : "r"(addr));
}
__device__ __forceinline__ void mma16816(float (&d)[4], const uint32_t (&a)[4], const uint32_t* b) {
    asm volatile("mma.sync.aligned.m16n8k16.row.col.f32.bf16.bf16.f32 "
                 "{%0,%1,%2,%3}, {%4,%5,%6,%7}, {%8,%9}, {%0,%1,%2,%3};"
                 : "+f"(d[0]), "+f"(d[1]), "+f"(d[2]), "+f"(d[3])
                 : "r"(a[0]), "r"(a[1]), "r"(a[2]), "r"(a[3]), "r"(b[0]), "r"(b[1]));
}
__device__ __forceinline__ uint32_t pack2(__nv_bfloat16 a, __nv_bfloat16 b) {
    return (uint32_t)__bfloat16_as_ushort(a) | ((uint32_t)__bfloat16_as_ushort(b) << 16);
}
__device__ __forceinline__ void split4(float4 v, uint2& hi, uint2& lo) {
    __nv_bfloat16 hx = __float2bfloat16(v.x), hy = __float2bfloat16(v.y);
    __nv_bfloat16 hz = __float2bfloat16(v.z), hw = __float2bfloat16(v.w);
    hi = make_uint2(pack2(hx, hy), pack2(hz, hw));
    lo = make_uint2(pack2(__float2bfloat16(v.x - __bfloat162float(hx)),
                          __float2bfloat16(v.y - __bfloat162float(hy))),
                    pack2(__float2bfloat16(v.z - __bfloat162float(hz)),
                          __float2bfloat16(v.w - __bfloat162float(hw))));
}
__device__ __forceinline__ void cp16(uint32_t dst, const void* src, int sz) {
    asm volatile("cp.async.cg.shared.global [%0], [%1], 16, %2;" :: "r"(dst), "l"(src), "r"(sz));
}
#define CP_COMMIT() asm volatile("cp.async.commit_group;" ::: "memory")
#define CP_WAIT0()  asm volatile("cp.async.wait_group 0;" ::: "memory")

// ---------------- HMMA GEMM with cp.async pipeline ----------------
// C[M,Ncols] = A[M,K] @ W[K,Ncols] + bias (+res)(relu)
// bf16 hi/lo compensated split (3 mma products) ~ fp32 precision.
// Block tile: 128m x (WN*32)n, threads = WN*64. Warp tile 64x32. K-chunk 32.
template <int WN, bool RES, bool RELU>
__global__ void __launch_bounds__(WN * 64, (WN == 4) ? 2 : 1)
mma_gemm(const float* __restrict__ A, const float* __restrict__ W,
         const float* __restrict__ bias, const float* __restrict__ res,
         float* __restrict__ C, int M, int Ncols, int K)
{
    constexpr int NT = WN * 32;
    constexpr int THREADS = WN * 64;
    constexpr int B_PITCH = NT + 8;                 // bf16 elems
    constexpr uint32_t SG_A = 0;                    // fp32 staging A: 128 x 36 f32
    constexpr uint32_t SG_B = 18432;                // fp32 staging B: 32 x NT f32
    constexpr uint32_t SA_HI = SG_B + 32 * NT * 4;
    constexpr uint32_t SA_LO = SA_HI + 10240;       // 128 x 40 bf16
    constexpr uint32_t SB_HI = SA_LO + 10240;
    constexpr uint32_t SB_LO = SB_HI + 32 * B_PITCH * 2;

    extern __shared__ __align__(16) uint8_t sm[];
    const uint32_t sb = smem_u32(sm);
    const int tid = threadIdx.x, wid = tid >> 5, lid = tid & 31;
    const int m0 = blockIdx.x * 128, n0 = blockIdx.y * NT;
    const int wm = wid / WN, wn = wid % WN;

    float acc[4][4][4];
#pragma unroll
    for (int i = 0; i < 4; i++)
#pragma unroll
        for (int j = 0; j < 4; j++)
#pragma unroll
            for (int q = 0; q < 4; q++) acc[i][j][q] = 0.f;

    // ---- cp.async staging of one 32-k chunk ----
    auto stage = [&](int kb) {
#pragma unroll
        for (int i = 0; i < 1024 / THREADS; i++) {
            int c = tid + i * THREADS;              // 16B chunk id for A
            int row = c >> 3, kq = c & 7;
            bool ok = (m0 + row) < M;
            const float* src = A + (size_t)(ok ? m0 + row : 0) * K + kb + kq * 4;
            cp16(sb + SG_A + (uint32_t)row * 144 + (uint32_t)kq * 16, src, ok ? 16 : 0);
        }
#pragma unroll
        for (int i = 0; i < (8 * NT) / THREADS; i++) {
            int c = tid + i * THREADS;              // 16B chunk id for B
            int k = c / (NT / 4), nq = c % (NT / 4);
            const float* src = W + (size_t)(kb + k) * Ncols + n0 + nq * 4;
            cp16(sb + SG_B + ((uint32_t)k * NT + (uint32_t)nq * 4) * 4, src, 16);
        }
        CP_COMMIT();
    };
    // ---- convert staged fp32 -> bf16 hi/lo mma layout ----
    auto convert = [&]() {
#pragma unroll
        for (int i = 0; i < 1024 / THREADS; i++) {
            int c = tid + i * THREADS;
            int row = c >> 3, kq = c & 7;
            float4 v = *(const float4*)(sm + SG_A + (uint32_t)row * 144 + (uint32_t)kq * 16);
            uint2 hi, lo;
            split4(v, hi, lo);
            uint32_t off = (uint32_t)row * 80 + (uint32_t)kq * 8;
            *(uint2*)(sm + SA_HI + off) = hi;
            *(uint2*)(sm + SA_LO + off) = lo;
        }
#pragma unroll
        for (int i = 0; i < (8 * NT) / THREADS; i++) {
            int c = tid + i * THREADS;
            int k = c / (NT / 4), nq = c % (NT / 4);
            float4 v = *(const float4*)(sm + SG_B + ((uint32_t)k * NT + (uint32_t)nq * 4) * 4);
            uint2 hi, lo;
            split4(v, hi, lo);
            uint32_t off = (uint32_t)k * (B_PITCH * 2) + (uint32_t)nq * 8;
            *(uint2*)(sm + SB_HI + off) = hi;
            *(uint2*)(sm + SB_LO + off) = lo;
        }
    };

    stage(0);
    CP_WAIT0();
    __syncthreads();
    convert();
    __syncthreads();

    for (int kb = 0; kb < K; kb += 32) {
        if (kb + 32 < K) stage(kb + 32);

        // ---- compute chunk ----
#pragma unroll
        for (int ks = 0; ks < 32; ks += 16) {
            uint32_t bhi[4][2], blo[4][2];
            const uint32_t brow = (uint32_t)(ks + (lid & 15)) * (B_PITCH * 2)
                                + (uint32_t)((lid >> 4) << 3) * 2;
#pragma unroll
            for (int p = 0; p < 2; p++) {
                uint32_t baddr = sb + brow + (uint32_t)(wn * 32 + p * 16) * 2;
                uint32_t r[4];
                ldsm4t(r, SB_HI + baddr);
                bhi[2 * p][0] = r[0]; bhi[2 * p][1] = r[1];
                bhi[2 * p + 1][0] = r[2]; bhi[2 * p + 1][1] = r[3];
                ldsm4t(r, SB_LO + baddr);
                blo[2 * p][0] = r[0]; blo[2 * p][1] = r[1];
                blo[2 * p + 1][0] = r[2]; blo[2 * p + 1][1] = r[3];
            }
            const uint32_t arow = (uint32_t)(wm * 64 + (lid & 15)) * 80
                                + (uint32_t)ks * 2 + (uint32_t)(lid >> 4) * 16;
#pragma unroll
            for (int mt = 0; mt < 4; mt++) {
                uint32_t aaddr = sb + arow + (uint32_t)mt * (16 * 80);
                uint32_t ahi4[4], alo4[4];
                ldsm4(ahi4, SA_HI + aaddr);
                ldsm4(alo4, SA_LO + aaddr);
#pragma unroll
                for (int nt = 0; nt < 4; nt++) {
                    mma16816(acc[mt][nt], ahi4, bhi[nt]);
                    mma16816(acc[mt][nt], ahi4, blo[nt]);
                    mma16816(acc[mt][nt], alo4, bhi[nt]);
                }
            }
        }

        if (kb + 32 < K) {
            CP_WAIT0();
            __syncthreads();
            convert();
            __syncthreads();
        }
    }

    // ---- epilogue ----
    const int qr = lid >> 2, qc = (lid & 3) * 2;
#pragma unroll
    for (int mt = 0; mt < 4; mt++) {
#pragma unroll
        for (int nt = 0; nt < 4; nt++) {
            int col = n0 + wn * 32 + nt * 8 + qc;
            float b0 = bias[col], b1 = bias[col + 1];
#pragma unroll
            for (int half = 0; half < 2; half++) {
                int row = m0 + wm * 64 + mt * 16 + qr + half * 8;
                if (row >= M) continue;
                float o0 = acc[mt][nt][half * 2 + 0] + b0;
                float o1 = acc[mt][nt][half * 2 + 1] + b1;
                if (RES) {
                    const float2 rr = *(const float2*)(res + (size_t)row * Ncols + col);
                    o0 += rr.x; o1 += rr.y;
                }
                if (RELU) { o0 = fmaxf(o0, 0.f); o1 = fmaxf(o1, 0.f); }
                *(float2*)(C + (size_t)row * Ncols + col) = make_float2(o0, o1);
            }
        }
    }
}

// ---------------- misc ----------------
__device__ __forceinline__ void atomicMaxF(float* addr, float v) {
    if (v >= 0.f) atomicMax((int*)addr, __float_as_int(v));
    else          atomicMin((unsigned int*)addr, __float_as_uint(v));
}

__global__ void fill_kernel(float* p, float v, int n) {
    int i = blockIdx.x * blockDim.x + threadIdx.x;
    if (i < n) p[i] = v;
}

// ---------------- edge kernels ----------------
union U16 { float4 q[4]; float f[16]; };

__global__ void edge_pass1(const int* __restrict__ ei, const float* __restrict__ Aw,
                           float* __restrict__ et, float* __restrict__ lg,
                           float* __restrict__ mx,
                           const float* __restrict__ Qh, const float* __restrict__ Kh,
                           const float* __restrict__ Ee)
{
    __shared__ float sAw[DIM];
    if (threadIdx.x < DIM) sAw[threadIdx.x] = Aw[threadIdx.x];
    __syncthreads();
    int t = blockIdx.x * blockDim.x + threadIdx.x;
    if (t >= NE * NH) return;
    int e = t >> 3, h = t & 7;
    int src = ei[e], dst = ei[NE + e];

    U16 K4, Q4, Wn, Bn, ET;
    const float4* kp = (const float4*)(Kh + (size_t)src * DIM + h * DH);
    const float4* qp = (const float4*)(Qh + (size_t)dst * DIM + h * DH);
    const float4* wp = (const float4*)(Ee + (size_t)e * (2 * DIM) + h * (2 * DH));
#pragma unroll
    for (int q = 0; q < 4; q++) {
        K4.q[q] = kp[q]; Q4.q[q] = qp[q];
        Wn.q[q] = wp[q]; Bn.q[q] = wp[q + 4];
    }
    float logit = 0.f;
#pragma unroll
    for (int d = 0; d < 16; d++) {
        float s = (K4.f[d] + Q4.f[d]) * Wn.f[d];
        float a = fabsf(s);
        float r = (a > 0.f) ? copysignf(sqrtf(a), s) : 0.f;
        float v = fmaxf(r + Bn.f[d], 0.f);
        ET.f[d] = v;
        logit = fmaf(v, sAw[d * NH + h], logit);
    }
    logit = fminf(fmaxf(logit, -5.f), 5.f);
    float4* ep = (float4*)(et + (size_t)e * DIM + h * DH);
#pragma unroll
    for (int q = 0; q < 4; q++) ep[q] = ET.q[q];
    lg[t] = logit;
    atomicMaxF(&mx[dst * NH + h], logit);
}

__global__ void edge_pass2(const int* __restrict__ ei, float* __restrict__ lg,
                           const float* __restrict__ mx, float* __restrict__ den)
{
    int t = blockIdx.x * blockDim.x + threadIdx.x;
    if (t >= NE * NH) return;
    int e = t >> 3, h = t & 7;
    int dst = ei[NE + e];
    float ex = expf(lg[t] - mx[dst * NH + h]);
    lg[t] = ex;
    atomicAdd(&den[dst * NH + h], ex);
}

__global__ void edge_pass3(const int* __restrict__ ei, const float* __restrict__ lg,
                           const float* __restrict__ den,
                           const float* __restrict__ Vh, const float* __restrict__ et,
                           float* __restrict__ wV, float* __restrict__ rowV)
{
    int t = blockIdx.x * blockDim.x + threadIdx.x;
    if (t >= NE * NH) return;
    int e = t >> 3, h = t & 7;
    int src = ei[e], dst = ei[NE + e];
    float attn = lg[t] / (den[dst * NH + h] + 1e-16f);
    U16 V4, E4;
    const float4* vp = (const float4*)(Vh + (size_t)src * DIM + h * DH);
    const float4* ep = (const float4*)(et + (size_t)e * DIM + h * DH);
#pragma unroll
    for (int q = 0; q < 4; q++) { V4.q[q] = vp[q]; E4.q[q] = ep[q]; }
    float* wv = wV + (size_t)dst * DIM + h * DH;
    float* rv = rowV + (size_t)dst * DIM + h * DH;
#pragma unroll
    for (int d = 0; d < 16; d++) {
        atomicAdd(&wv[d], V4.f[d] * attn);
        atomicAdd(&rv[d], E4.f[d] * attn);
    }
}

// ---------------- node combine ----------------
__global__ void node_fix(const float* __restrict__ wV, const float* __restrict__ rowV,
                         const float* __restrict__ VeRow, const float* __restrict__ log_deg,
                         const float* __restrict__ deg_coef, float* __restrict__ hatt)
{
    int t = blockIdx.x * blockDim.x + threadIdx.x;
    if (t >= NN * DIM) return;
    int n = t >> 7, c = t & 127, h = c >> 4, co = c & 15;
    float acc = wV[t];
    const float* rv = rowV + (size_t)n * DIM + h * DH;
#pragma unroll
    for (int d2 = 0; d2 < 16; d2++)
        acc = fmaf(rv[d2], VeRow[d2 * DIM + h * DH + co], acc);
    float ld = log_deg[n];
    hatt[t] = acc * (deg_coef[2 * c] + ld * deg_coef[2 * c + 1]);
}

// ---------------- batch norm ----------------
__global__ void bn_stats(const float* __restrict__ v, int M, float* __restrict__ sums)
{
    int c = threadIdx.x;
    float s = 0.f, s2 = 0.f;
    for (int r = blockIdx.x; r < M; r += gridDim.x) {
        float x = v[(size_t)r * DIM + c];
        s += x;
        s2 = fmaf(x, x, s2);
    }
    atomicAdd(&sums[c], s);
    atomicAdd(&sums[DIM + c], s2);
}

__global__ void bn_apply(const float* __restrict__ v, float* __restrict__ out, int M,
                         const float* __restrict__ sums,
                         const float* __restrict__ g, const float* __restrict__ b, float invM)
{
    long long total = (long long)M * DIM;
    long long i = (long long)blockIdx.x * blockDim.x + threadIdx.x;
    if (i >= total) return;
    int c = (int)(i & (DIM - 1));
    float m = sums[c] * invM;
    float var = fmaf(-m, m, sums[DIM + c] * invM);
    out[i] = (v[i] - m) * rsqrtf(var + 1e-5f) * g[c] + b[c];
}

// ---------------- launch ----------------
extern "C" void kernel_launch(void* const* d_in, const int* in_sizes, int n_in,
                              void* d_out, int out_size)
{
    const float* x         = (const float*)d_in[0];
    const float* edge_attr = (const float*)d_in[1];
    const int*   ei        = (const int*)d_in[2];
    const float* log_deg   = (const float*)d_in[3];
    const float* Wq = (const float*)d_in[4],  *bq  = (const float*)d_in[5];
    const float* Wk = (const float*)d_in[6],  *bk  = (const float*)d_in[7];
    const float* We = (const float*)d_in[8],  *be  = (const float*)d_in[9];
    const float* Wv = (const float*)d_in[10], *bv  = (const float*)d_in[11];
    const float* Aw = (const float*)d_in[12], *VeRow = (const float*)d_in[13];
    const float* WOh = (const float*)d_in[14], *bOh = (const float*)d_in[15];
    const float* WOe = (const float*)d_in[16], *bOe = (const float*)d_in[17];
    const float* deg_coef = (const float*)d_in[18];
    const float* g1h = (const float*)d_in[19], *b1h = (const float*)d_in[20];
    const float* g1e = (const float*)d_in[21], *b1e = (const float*)d_in[22];
    const float* g2h = (const float*)d_in[23], *b2h = (const float*)d_in[24];
    const float* W1 = (const float*)d_in[25], *b1 = (const float*)d_in[26];
    const float* W2 = (const float*)d_in[27], *b2 = (const float*)d_in[28];

    float *Qh, *Kh, *Vh, *Ee, *et, *lg, *mx, *den, *wV, *rowV, *hatt, *v1, *hbn, *h2a, *v2, *s1, *s2, *se;
    cudaGetSymbolAddress((void**)&Qh, g_Qh);
    cudaGetSymbolAddress((void**)&Kh, g_Kh);
    cudaGetSymbolAddress((void**)&Vh, g_Vh);
    cudaGetSymbolAddress((void**)&Ee, g_Ee);
    cudaGetSymbolAddress((void**)&et, g_et);
    cudaGetSymbolAddress((void**)&lg, g_lg);
    cudaGetSymbolAddress((void**)&mx, g_mx);
    cudaGetSymbolAddress((void**)&den, g_den);
    cudaGetSymbolAddress((void**)&wV, g_wV);
    cudaGetSymbolAddress((void**)&rowV, g_rowV);
    cudaGetSymbolAddress((void**)&hatt, g_hatt);
    cudaGetSymbolAddress((void**)&v1, g_v1);
    cudaGetSymbolAddress((void**)&hbn, g_hbn);
    cudaGetSymbolAddress((void**)&h2a, g_h2a);
    cudaGetSymbolAddress((void**)&v2, g_v2);
    cudaGetSymbolAddress((void**)&s1, g_s1);
    cudaGetSymbolAddress((void**)&s2, g_s2);
    cudaGetSymbolAddress((void**)&se, g_se);

    float* hout = (float*)d_out;
    float* eout = (float*)d_out + (size_t)NN * DIM;

    // dynamic smem sizes
    const int SM4 = 72704;    // WN=4
    const int SM8 = 105472;   // WN=8
    cudaFuncSetAttribute(mma_gemm<4, false, false>, cudaFuncAttributeMaxDynamicSharedMemorySize, SM4);
    cudaFuncSetAttribute(mma_gemm<4, true,  false>, cudaFuncAttributeMaxDynamicSharedMemorySize, SM4);
    cudaFuncSetAttribute(mma_gemm<8, false, false>, cudaFuncAttributeMaxDynamicSharedMemorySize, SM8);
    cudaFuncSetAttribute(mma_gemm<8, false, true >, cudaFuncAttributeMaxDynamicSharedMemorySize, SM8);

    // init accumulators
    cudaMemsetAsync(wV, 0, (size_t)NN * DIM * sizeof(float));
    cudaMemsetAsync(rowV, 0, (size_t)NN * DIM * sizeof(float));
    cudaMemsetAsync(den, 0, (size_t)NN * NH * sizeof(float));
    cudaMemsetAsync(s1, 0, 2 * DIM * sizeof(float));
    cudaMemsetAsync(s2, 0, 2 * DIM * sizeof(float));
    cudaMemsetAsync(se, 0, 2 * DIM * sizeof(float));
    fill_kernel<<<cdiv(NN * NH, 256), 256>>>(mx, -1e30f, NN * NH);

    const int gN = cdiv(NN, 128), gE = cdiv(NE, 128);

    // projections
    mma_gemm<4, false, false><<<dim3(gN, 1), 256, SM4>>>(x, Wq, bq, nullptr, Qh, NN, 128, 128);
    mma_gemm<4, false, false><<<dim3(gN, 1), 256, SM4>>>(x, Wk, bk, nullptr, Kh, NN, 128, 128);
    mma_gemm<4, false, false><<<dim3(gN, 1), 256, SM4>>>(x, Wv, bv, nullptr, Vh, NN, 128, 128);
    mma_gemm<8, false, false><<<dim3(gE, 1), 512, SM8>>>(edge_attr, We, be, nullptr, Ee, NE, 256, 128);

    // attention (3 edge passes)
    int eth = NE * NH;
    edge_pass1<<<cdiv(eth, 256), 256>>>(ei, Aw, et, lg, mx, Qh, Kh, Ee);
    edge_pass2<<<cdiv(eth, 256), 256>>>(ei, lg, mx, den);
    edge_pass3<<<cdiv(eth, 256), 256>>>(ei, lg, den, Vh, et, wV, rowV);

    // node combine + degree scaler
    node_fix<<<cdiv(NN * DIM, 256), 256>>>(wV, rowV, VeRow, log_deg, deg_coef, hatt);

    // h path: out proj + residual + BN1
    mma_gemm<4, true, false><<<dim3(gN, 1), 256, SM4>>>(hatt, WOh, bOh, x, v1, NN, 128, 128);
    bn_stats<<<1024, 128>>>(v1, NN, s1);
    bn_apply<<<cdiv((long long)NN * DIM, 256), 256>>>(v1, hbn, NN, s1, g1h, b1h, 1.f / NN);

    // e path: out proj + residual + BN (written into output)
    mma_gemm<4, true, false><<<dim3(gE, 1), 256, SM4>>>(et, WOe, bOe, edge_attr, eout, NE, 128, 128);
    bn_stats<<<4096, 128>>>(eout, NE, se);
    bn_apply<<<cdiv((long long)NE * DIM, 256), 256>>>(eout, eout, NE, se, g1e, b1e, 1.f / NE);

    // FFN + BN2
    mma_gemm<8, false, true><<<dim3(gN, 1), 512, SM8>>>(hbn, W1, b1, nullptr, h2a, NN, 256, 128);
    mma_gemm<4, true, false><<<dim3(gN, 1), 256, SM4>>>(h2a, W2, b2, hbn, v2, NN, 128, 256);
    bn_stats<<<1024, 128>>>(v2, NN, s2);
    bn_apply<<<cdiv((long long)NN * DIM, 256), 256>>>(v2, hout, NN, s2, g2h, b2h, 1.f / NN);
}

// round 5
// speedup vs baseline: 1.2910x; 1.2910x over previous
#include <cuda_runtime.h>
#include <cuda_bf16.h>
#include <math.h>
#include <stdint.h>

#define NN 40000
#define NE 640000
#define DIM 128
#define NH 8
#define DH 16

// ---------------- scratch (device globals: allocation-free) ----------------
__device__ float g_Qh[(size_t)NN * DIM];
__device__ float g_Kh[(size_t)NN * DIM];
__device__ float g_Vh[(size_t)NN * DIM];
__device__ float g_et[(size_t)NE * DIM];
__device__ float g_lg[(size_t)NE * NH];
__device__ float g_mx[(size_t)NN * NH];
__device__ float g_den[(size_t)NN * NH];
__device__ float g_wV[(size_t)NN * DIM];
__device__ float g_rowV[(size_t)NN * DIM];
__device__ float g_hatt[(size_t)NN * DIM];
__device__ float g_v1[(size_t)NN * DIM];
__device__ float g_hbn[(size_t)NN * DIM];
__device__ float g_h2a[(size_t)NN * 2 * DIM];
__device__ float g_v2[(size_t)NN * DIM];
__device__ float g_s1[2 * DIM];
__device__ float g_s2[2 * DIM];
__device__ float g_se[2 * DIM];

static inline int cdiv(long long a, long long b) { return (int)((a + b - 1) / b); }

// ---------------- mma helpers ----------------
__device__ __forceinline__ uint32_t smem_u32(const void* p) {
    uint32_t a;
    asm("{ .reg .u64 t; cvta.to.shared.u64 t, %1; cvt.u32.u64 %0, t; }" : "=r"(a) : "l"(p));
    return a;
}
__device__ __forceinline__ void ldsm4(uint32_t (&r)[4], uint32_t addr) {
    asm volatile("ldmatrix.sync.aligned.m8n8.x4.shared.b16 {%0,%1,%2,%3}, [%4];"
                 : "=r"(r[0]), "=r"(r[1]), "=r"(r[2]), "=r"(r[3]) : "r"(addr));
}
__device__ __forceinline__ void ldsm4t(uint32_t (&r)[4], uint32_t addr) {
    asm volatile("ldmatrix.sync.aligned.m8n8.x4.trans.shared.b16 {%0,%1,%2,%3}, [%4];"
                 : "=r"(r[0]), "=r"(r[1]), "=r"(r[2]), "=r"(r[3]) : "r"(addr));
}
__device__ __forceinline__ void mma16816(float (&d)[4], const uint32_t (&a)[4], const uint32_t* b) {
    asm volatile("mma.sync.aligned.m16n8k16.row.col.f32.bf16.bf16.f32 "
                 "{%0,%1,%2,%3}, {%4,%5,%6,%7}, {%8,%9}, {%0,%1,%2,%3};"
                 : "+f"(d[0]), "+f"(d[1]), "+f"(d[2]), "+f"(d[3])
                 : "r"(a[0]), "r"(a[1]), "r"(a[2]), "r"(a[3]), "r"(b[0]), "r"(b[1]));
}
__device__ __forceinline__ uint32_t pack2(__nv_bfloat16 a, __nv_bfloat16 b) {
    return (uint32_t)__bfloat16_as_ushort(a) | ((uint32_t)__bfloat16_as_ushort(b) << 16);
}
__device__ __forceinline__ void split4(float4 v, uint2& hi, uint2& lo) {
    __nv_bfloat16 hx = __float2bfloat16(v.x), hy = __float2bfloat16(v.y);
    __nv_bfloat16 hz = __float2bfloat16(v.z), hw = __float2bfloat16(v.w);
    hi = make_uint2(pack2(hx, hy), pack2(hz, hw));
    lo = make_uint2(pack2(__float2bfloat16(v.x - __bfloat162float(hx)),
                          __float2bfloat16(v.y - __bfloat162float(hy))),
                    pack2(__float2bfloat16(v.z - __bfloat162float(hz)),
                          __float2bfloat16(v.w - __bfloat162float(hw))));
}
__device__ __forceinline__ void cp16(uint32_t dst, const void* src, int sz) {
    asm volatile("cp.async.cg.shared.global [%0], [%1], 16, %2;" :: "r"(dst), "l"(src), "r"(sz));
}
#define CP_COMMIT() asm volatile("cp.async.commit_group;" ::: "memory")
#define CP_WAIT0()  asm volatile("cp.async.wait_group 0;" ::: "memory")

__device__ __forceinline__ void atomicMaxF(float* addr, float v) {
    if (v >= 0.f) atomicMax((int*)addr, __float_as_int(v));
    else          atomicMin((unsigned int*)addr, __float_as_uint(v));
}
__device__ __forceinline__ void red4(float* p, float a, float b, float c, float d) {
    asm volatile("red.global.add.v4.f32 [%0], {%1,%2,%3,%4};"
                 :: "l"(p), "f"(a), "f"(b), "f"(c), "f"(d) : "memory");
}

// ---------------- smem layout constants (WN=4, 256 threads, k-chunk 32) ----
#define B_PITCH 136
#define SG_A 0u
#define SG_B 18432u
#define SA_HI 34816u
#define SA_LO 45056u
#define SB_HI 55296u
#define SB_LO 64000u
#define SM_TOTAL 72704

// ---- shared GEMM machinery for 128x128 block tile (WN=4) ----
struct GemmCore {
    uint32_t sb;
    int tid, wid, lid, wm, wn, m0, n0;
    float acc[4][4][4];

    __device__ __forceinline__ void init(uint8_t* sm, int bm, int bn) {
        sb = smem_u32(sm);
        tid = threadIdx.x; wid = tid >> 5; lid = tid & 31;
        wm = wid >> 2; wn = wid & 3;
        m0 = bm * 128; n0 = bn * 128;
#pragma unroll
        for (int i = 0; i < 4; i++)
#pragma unroll
            for (int j = 0; j < 4; j++)
#pragma unroll
                for (int q = 0; q < 4; q++) acc[i][j][q] = 0.f;
    }
    __device__ __forceinline__ void stage(uint8_t* sm, const float* A, const float* W,
                                          int M, int Ncols, int K, int kb) {
#pragma unroll
        for (int i = 0; i < 4; i++) {
            int c = tid + i * 256;
            int row = c >> 3, kq = c & 7;
            bool ok = (m0 + row) < M;
            const float* src = A + (size_t)(ok ? m0 + row : 0) * K + kb + kq * 4;
            cp16(sb + SG_A + (uint32_t)row * 144 + (uint32_t)kq * 16, src, ok ? 16 : 0);
        }
#pragma unroll
        for (int i = 0; i < 4; i++) {
            int c = tid + i * 256;
            int k = c >> 5, nq = c & 31;
            const float* src = W + (size_t)(kb + k) * Ncols + n0 + nq * 4;
            cp16(sb + SG_B + ((uint32_t)k * 128 + (uint32_t)nq * 4) * 4, src, 16);
        }
        CP_COMMIT();
    }
    __device__ __forceinline__ void convert(uint8_t* sm) {
#pragma unroll
        for (int i = 0; i < 4; i++) {
            int c = tid + i * 256;
            int row = c >> 3, kq = c & 7;
            float4 v = *(const float4*)(sm + SG_A + (uint32_t)row * 144 + (uint32_t)kq * 16);
            uint2 hi, lo;
            split4(v, hi, lo);
            uint32_t off = (uint32_t)row * 80 + (uint32_t)kq * 8;
            *(uint2*)(sm + SA_HI + off) = hi;
            *(uint2*)(sm + SA_LO + off) = lo;
        }
#pragma unroll
        for (int i = 0; i < 4; i++) {
            int c = tid + i * 256;
            int k = c >> 5, nq = c & 31;
            float4 v = *(const float4*)(sm + SG_B + ((uint32_t)k * 128 + (uint32_t)nq * 4) * 4);
            uint2 hi, lo;
            split4(v, hi, lo);
            uint32_t off = (uint32_t)k * (B_PITCH * 2) + (uint32_t)nq * 8;
            *(uint2*)(sm + SB_HI + off) = hi;
            *(uint2*)(sm + SB_LO + off) = lo;
        }
    }
    __device__ __forceinline__ void compute_chunk() {
#pragma unroll
        for (int ks = 0; ks < 32; ks += 16) {
            uint32_t bhi[4][2], blo[4][2];
            const uint32_t brow = (uint32_t)(ks + (lid & 15)) * (B_PITCH * 2)
                                + (uint32_t)((lid >> 4) << 3) * 2;
#pragma unroll
            for (int p = 0; p < 2; p++) {
                uint32_t baddr = sb + brow + (uint32_t)(wn * 32 + p * 16) * 2;
                uint32_t r[4];
                ldsm4t(r, SB_HI + baddr);
                bhi[2 * p][0] = r[0]; bhi[2 * p][1] = r[1];
                bhi[2 * p + 1][0] = r[2]; bhi[2 * p + 1][1] = r[3];
                ldsm4t(r, SB_LO + baddr);
                blo[2 * p][0] = r[0]; blo[2 * p][1] = r[1];
                blo[2 * p + 1][0] = r[2]; blo[2 * p + 1][1] = r[3];
            }
            const uint32_t arow = (uint32_t)(wm * 64 + (lid & 15)) * 80
                                + (uint32_t)ks * 2 + (uint32_t)(lid >> 4) * 16;
#pragma unroll
            for (int mt = 0; mt < 4; mt++) {
                uint32_t aaddr = sb + arow + (uint32_t)mt * (16 * 80);
                uint32_t ahi4[4], alo4[4];
                ldsm4(ahi4, SA_HI + aaddr);
                ldsm4(alo4, SA_LO + aaddr);
#pragma unroll
                for (int nt = 0; nt < 4; nt++) {
                    mma16816(acc[mt][nt], ahi4, bhi[nt]);
                    mma16816(acc[mt][nt], ahi4, blo[nt]);
                    mma16816(acc[mt][nt], alo4, bhi[nt]);
                }
            }
        }
    }
    __device__ __forceinline__ void mainloop(uint8_t* sm, const float* A, const float* W,
                                             int M, int Ncols, int K) {
        stage(sm, A, W, M, Ncols, K, 0);
        CP_WAIT0();
        __syncthreads();
        convert(sm);
        __syncthreads();
        for (int kb = 0; kb < K; kb += 32) {
            if (kb + 32 < K) stage(sm, A, W, M, Ncols, K, kb + 32);
            compute_chunk();
            if (kb + 32 < K) {
                CP_WAIT0();
                __syncthreads();
                convert(sm);
                __syncthreads();
            }
        }
    }
};

// ---------------- generic GEMM kernel ----------------
template <bool RES, bool RELU>
__global__ void __launch_bounds__(256, 2)
mma_gemm(const float* __restrict__ A, const float* __restrict__ W,
         const float* __restrict__ bias, const float* __restrict__ res,
         float* __restrict__ C, int M, int Ncols, int K)
{
    extern __shared__ __align__(16) uint8_t sm[];
    GemmCore g;
    g.init(sm, blockIdx.x, blockIdx.y);
    g.mainloop(sm, A, W, M, Ncols, K);

    const int qr = g.lid >> 2, qc = (g.lid & 3) * 2;
#pragma unroll
    for (int mt = 0; mt < 4; mt++) {
#pragma unroll
        for (int nt = 0; nt < 4; nt++) {
            int col = g.n0 + g.wn * 32 + nt * 8 + qc;
            float b0 = bias[col], b1 = bias[col + 1];
#pragma unroll
            for (int half = 0; half < 2; half++) {
                int row = g.m0 + g.wm * 64 + mt * 16 + qr + half * 8;
                if (row >= M) continue;
                float o0 = g.acc[mt][nt][half * 2 + 0] + b0;
                float o1 = g.acc[mt][nt][half * 2 + 1] + b1;
                if (RES) {
                    const float2 rr = *(const float2*)(res + (size_t)row * Ncols + col);
                    o0 += rr.x; o1 += rr.y;
                }
                if (RELU) { o0 = fmaxf(o0, 0.f); o1 = fmaxf(o1, 0.f); }
                *(float2*)(C + (size_t)row * Ncols + col) = make_float2(o0, o1);
            }
        }
    }
}

// ---------------- fused Ee GEMM + edge score/logit (replaces pass1) --------
// Block (bx, by): edges [bx*128, bx*128+128), heads [by*4, by*4+4).
// Cols [by*128, by*128+128) of Ee contain E_w and E_b for those 4 heads.
union U16 { float4 q[4]; float f[16]; };

__global__ void __launch_bounds__(256, 2)
edge_gemm_fused(const float* __restrict__ A, const float* __restrict__ W,
                const float* __restrict__ bias,
                const int* __restrict__ ei, const float* __restrict__ Aw,
                const float* __restrict__ Qh, const float* __restrict__ Kh,
                float* __restrict__ et, float* __restrict__ lg, float* __restrict__ mx)
{
    extern __shared__ __align__(16) uint8_t sm[];
    __shared__ float sAw[DIM];
    if (threadIdx.x < DIM) sAw[threadIdx.x] = Aw[threadIdx.x];

    GemmCore g;
    g.init(sm, blockIdx.x, blockIdx.y);
    g.mainloop(sm, A, W, NE, 256, 128);

    __syncthreads();   // tiles dead; reuse smem for the output tile
    float* sC = (float*)sm;          // 128 rows x 132 pitch
    const int qr = g.lid >> 2, qc = (g.lid & 3) * 2;
#pragma unroll
    for (int mt = 0; mt < 4; mt++) {
#pragma unroll
        for (int nt = 0; nt < 4; nt++) {
            int col = g.wn * 32 + nt * 8 + qc;
            float b0 = bias[g.n0 + col], b1 = bias[g.n0 + col + 1];
#pragma unroll
            for (int half = 0; half < 2; half++) {
                int row = g.wm * 64 + mt * 16 + qr + half * 8;
                *(float2*)(sC + row * 132 + col) =
                    make_float2(g.acc[mt][nt][half * 2 + 0] + b0,
                                g.acc[mt][nt][half * 2 + 1] + b1);
            }
        }
    }
    __syncthreads();

    // ---- per-(edge, head) score -> e_t, logit, segment-max ----
    const int e = threadIdx.x & 127;
    const int ge = g.m0 + e;                    // NE % 128 == 0
    const int src = ei[ge], dst = ei[NE + ge];
#pragma unroll
    for (int u = 0; u < 2; u++) {
        const int hl = (threadIdx.x >> 7) * 2 + u;
        const int h = blockIdx.y * 4 + hl;
        const float* ew = sC + e * 132 + hl * 32;
        U16 K4, Q4, EW, EB, ET;
        const float4* kp = (const float4*)(Kh + (size_t)src * DIM + h * DH);
        const float4* qp = (const float4*)(Qh + (size_t)dst * DIM + h * DH);
#pragma unroll
        for (int q = 0; q < 4; q++) {
            K4.q[q] = kp[q]; Q4.q[q] = qp[q];
            EW.q[q] = *(const float4*)(ew + q * 4);
            EB.q[q] = *(const float4*)(ew + 16 + q * 4);
        }
        float logit = 0.f;
#pragma unroll
        for (int d = 0; d < 16; d++) {
            float s = (K4.f[d] + Q4.f[d]) * EW.f[d];
            float a = fabsf(s);
            float r = (a > 0.f) ? copysignf(sqrtf(a), s) : 0.f;
            float v = fmaxf(r + EB.f[d], 0.f);
            ET.f[d] = v;
            logit = fmaf(v, sAw[d * NH + h], logit);
        }
        logit = fminf(fmaxf(logit, -5.f), 5.f);
        float4* ep = (float4*)(et + (size_t)ge * DIM + h * DH);
#pragma unroll
        for (int q = 0; q < 4; q++) ep[q] = ET.q[q];
        lg[ge * NH + h] = logit;
        atomicMaxF(&mx[dst * NH + h], logit);
    }
}

// ---------------- misc ----------------
__global__ void fill_kernel(float* p, float v, int n) {
    int i = blockIdx.x * blockDim.x + threadIdx.x;
    if (i < n) p[i] = v;
}

__global__ void edge_pass2(const int* __restrict__ ei, float* __restrict__ lg,
                           const float* __restrict__ mx, float* __restrict__ den)
{
    int t = blockIdx.x * blockDim.x + threadIdx.x;
    if (t >= NE * NH) return;
    int e = t >> 3, h = t & 7;
    int dst = ei[NE + e];
    float ex = expf(lg[t] - mx[dst * NH + h]);
    lg[t] = ex;
    atomicAdd(&den[dst * NH + h], ex);
}

__global__ void edge_pass3(const int* __restrict__ ei, const float* __restrict__ lg,
                           const float* __restrict__ den,
                           const float* __restrict__ Vh, const float* __restrict__ et,
                           float* __restrict__ wV, float* __restrict__ rowV)
{
    int t = blockIdx.x * blockDim.x + threadIdx.x;
    if (t >= NE * NH) return;
    int e = t >> 3, h = t & 7;
    int src = ei[e], dst = ei[NE + e];
    float attn = lg[t] / (den[dst * NH + h] + 1e-16f);
    U16 V4, E4;
    const float4* vp = (const float4*)(Vh + (size_t)src * DIM + h * DH);
    const float4* ep = (const float4*)(et + (size_t)e * DIM + h * DH);
#pragma unroll
    for (int q = 0; q < 4; q++) { V4.q[q] = vp[q]; E4.q[q] = ep[q]; }
    float* wv = wV + (size_t)dst * DIM + h * DH;
    float* rv = rowV + (size_t)dst * DIM + h * DH;
#pragma unroll
    for (int q = 0; q < 4; q++) {
        red4(wv + q * 4, V4.q[q].x * attn, V4.q[q].y * attn, V4.q[q].z * attn, V4.q[q].w * attn);
        red4(rv + q * 4, E4.q[q].x * attn, E4.q[q].y * attn, E4.q[q].z * attn, E4.q[q].w * attn);
    }
}

// ---------------- node combine ----------------
__global__ void node_fix(const float* __restrict__ wV, const float* __restrict__ rowV,
                         const float* __restrict__ VeRow, const float* __restrict__ log_deg,
                         const float* __restrict__ deg_coef, float* __restrict__ hatt)
{
    int t = blockIdx.x * blockDim.x + threadIdx.x;
    if (t >= NN * DIM) return;
    int n = t >> 7, c = t & 127, h = c >> 4, co = c & 15;
    float acc = wV[t];
    const float* rv = rowV + (size_t)n * DIM + h * DH;
#pragma unroll
    for (int d2 = 0; d2 < 16; d2++)
        acc = fmaf(rv[d2], VeRow[d2 * DIM + h * DH + co], acc);
    float ld = log_deg[n];
    hatt[t] = acc * (deg_coef[2 * c] + ld * deg_coef[2 * c + 1]);
}

// ---------------- batch norm ----------------
__global__ void bn_stats(const float* __restrict__ v, int M, float* __restrict__ sums)
{
    int c = threadIdx.x;
    float s = 0.f, s2 = 0.f;
    for (int r = blockIdx.x; r < M; r += gridDim.x) {
        float x = v[(size_t)r * DIM + c];
        s += x;
        s2 = fmaf(x, x, s2);
    }
    atomicAdd(&sums[c], s);
    atomicAdd(&sums[DIM + c], s2);
}

__global__ void bn_apply(const float* __restrict__ v, float* __restrict__ out, int M,
                         const float* __restrict__ sums,
                         const float* __restrict__ g, const float* __restrict__ b, float invM)
{
    long long total = (long long)M * DIM;
    long long i = (long long)blockIdx.x * blockDim.x + threadIdx.x;
    if (i >= total) return;
    int c = (int)(i & (DIM - 1));
    float m = sums[c] * invM;
    float var = fmaf(-m, m, sums[DIM + c] * invM);
    out[i] = (v[i] - m) * rsqrtf(var + 1e-5f) * g[c] + b[c];
}

// ---------------- launch ----------------
extern "C" void kernel_launch(void* const* d_in, const int* in_sizes, int n_in,
                              void* d_out, int out_size)
{
    const float* x         = (const float*)d_in[0];
    const float* edge_attr = (const float*)d_in[1];
    const int*   ei        = (const int*)d_in[2];
    const float* log_deg   = (const float*)d_in[3];
    const float* Wq = (const float*)d_in[4],  *bq  = (const float*)d_in[5];
    const float* Wk = (const float*)d_in[6],  *bk  = (const float*)d_in[7];
    const float* We = (const float*)d_in[8],  *be  = (const float*)d_in[9];
    const float* Wv = (const float*)d_in[10], *bv  = (const float*)d_in[11];
    const float* Aw = (const float*)d_in[12], *VeRow = (const float*)d_in[13];
    const float* WOh = (const float*)d_in[14], *bOh = (const float*)d_in[15];
    const float* WOe = (const float*)d_in[16], *bOe = (const float*)d_in[17];
    const float* deg_coef = (const float*)d_in[18];
    const float* g1h = (const float*)d_in[19], *b1h = (const float*)d_in[20];
    const float* g1e = (const float*)d_in[21], *b1e = (const float*)d_in[22];
    const float* g2h = (const float*)d_in[23], *b2h = (const float*)d_in[24];
    const float* W1 = (const float*)d_in[25], *b1 = (const float*)d_in[26];
    const float* W2 = (const float*)d_in[27], *b2 = (const float*)d_in[28];

    float *Qh, *Kh, *Vh, *et, *lg, *mx, *den, *wV, *rowV, *hatt, *v1, *hbn, *h2a, *v2, *s1, *s2, *se;
    cudaGetSymbolAddress((void**)&Qh, g_Qh);
    cudaGetSymbolAddress((void**)&Kh, g_Kh);
    cudaGetSymbolAddress((void**)&Vh, g_Vh);
    cudaGetSymbolAddress((void**)&et, g_et);
    cudaGetSymbolAddress((void**)&lg, g_lg);
    cudaGetSymbolAddress((void**)&mx, g_mx);
    cudaGetSymbolAddress((void**)&den, g_den);
    cudaGetSymbolAddress((void**)&wV, g_wV);
    cudaGetSymbolAddress((void**)&rowV, g_rowV);
    cudaGetSymbolAddress((void**)&hatt, g_hatt);
    cudaGetSymbolAddress((void**)&v1, g_v1);
    cudaGetSymbolAddress((void**)&hbn, g_hbn);
    cudaGetSymbolAddress((void**)&h2a, g_h2a);
    cudaGetSymbolAddress((void**)&v2, g_v2);
    cudaGetSymbolAddress((void**)&s1, g_s1);
    cudaGetSymbolAddress((void**)&s2, g_s2);
    cudaGetSymbolAddress((void**)&se, g_se);

    float* hout = (float*)d_out;
    float* eout = (float*)d_out + (size_t)NN * DIM;

    cudaFuncSetAttribute(mma_gemm<false, false>, cudaFuncAttributeMaxDynamicSharedMemorySize, SM_TOTAL);
    cudaFuncSetAttribute(mma_gemm<true,  false>, cudaFuncAttributeMaxDynamicSharedMemorySize, SM_TOTAL);
    cudaFuncSetAttribute(mma_gemm<false, true >, cudaFuncAttributeMaxDynamicSharedMemorySize, SM_TOTAL);
    cudaFuncSetAttribute(edge_gemm_fused, cudaFuncAttributeMaxDynamicSharedMemorySize, SM_TOTAL);

    // init accumulators
    cudaMemsetAsync(wV, 0, (size_t)NN * DIM * sizeof(float));
    cudaMemsetAsync(rowV, 0, (size_t)NN * DIM * sizeof(float));
    cudaMemsetAsync(den, 0, (size_t)NN * NH * sizeof(float));
    cudaMemsetAsync(s1, 0, 2 * DIM * sizeof(float));
    cudaMemsetAsync(s2, 0, 2 * DIM * sizeof(float));
    cudaMemsetAsync(se, 0, 2 * DIM * sizeof(float));
    fill_kernel<<<cdiv(NN * NH, 256), 256>>>(mx, -1e30f, NN * NH);

    const int gN = cdiv(NN, 128), gE = cdiv(NE, 128);

    // projections
    mma_gemm<false, false><<<dim3(gN, 1), 256, SM_TOTAL>>>(x, Wq, bq, nullptr, Qh, NN, 128, 128);
    mma_gemm<false, false><<<dim3(gN, 1), 256, SM_TOTAL>>>(x, Wk, bk, nullptr, Kh, NN, 128, 128);
    mma_gemm<false, false><<<dim3(gN, 1), 256, SM_TOTAL>>>(x, Wv, bv, nullptr, Vh, NN, 128, 128);

    // fused Ee GEMM + score/logit/segment-max (replaces Ee GEMM + pass1)
    edge_gemm_fused<<<dim3(gE, 2), 256, SM_TOTAL>>>(edge_attr, We, be, ei, Aw, Qh, Kh, et, lg, mx);

    // softmax denominator + attention-weighted scatter
    int eth = NE * NH;
    edge_pass2<<<cdiv(eth, 256), 256>>>(ei, lg, mx, den);
    edge_pass3<<<cdiv(eth, 256), 256>>>(ei, lg, den, Vh, et, wV, rowV);

    // node combine + degree scaler
    node_fix<<<cdiv(NN * DIM, 256), 256>>>(wV, rowV, VeRow, log_deg, deg_coef, hatt);

    // h path: out proj + residual + BN1
    mma_gemm<true, false><<<dim3(gN, 1), 256, SM_TOTAL>>>(hatt, WOh, bOh, x, v1, NN, 128, 128);
    bn_stats<<<1024, 128>>>(v1, NN, s1);
    bn_apply<<<cdiv((long long)NN * DIM, 256), 256>>>(v1, hbn, NN, s1, g1h, b1h, 1.f / NN);

    // e path: out proj + residual + BN (into output)
    mma_gemm<true, false><<<dim3(gE, 1), 256, SM_TOTAL>>>(et, WOe, bOe, edge_attr, eout, NE, 128, 128);
    bn_stats<<<4096, 128>>>(eout, NE, se);
    bn_apply<<<cdiv((long long)NE * DIM, 256), 256>>>(eout, eout, NE, se, g1e, b1e, 1.f / NE);

    // FFN + BN2
    mma_gemm<false, true><<<dim3(gN, 2), 256, SM_TOTAL>>>(hbn, W1, b1, nullptr, h2a, NN, 256, 128);
    mma_gemm<true, false><<<dim3(gN, 1), 256, SM_TOTAL>>>(h2a, W2, b2, hbn, v2, NN, 128, 256);
    bn_stats<<<1024, 128>>>(v2, NN, s2);
    bn_apply<<<cdiv((long long)NN * DIM, 256), 256>>>(v2, hout, NN, s2, g2h, b2h, 1.f / NN);
}

// round 6
// speedup vs baseline: 1.3678x; 1.0595x over previous
#include <cuda_runtime.h>
#include <cuda_bf16.h>
#include <math.h>
#include <stdint.h>

#define NN 40000
#define NE 640000
#define DIM 128
#define NH 8
#define DH 16

typedef __nv_bfloat16 bf16;

// ---------------- scratch (device globals: allocation-free) ----------------
__device__ float g_Qh[(size_t)NN * DIM];
__device__ float g_Kh[(size_t)NN * DIM];
__device__ float g_Vh[(size_t)NN * DIM];
__device__ float g_lg[(size_t)NE * NH];
__device__ float g_mx[(size_t)NN * NH];
__device__ float g_den[(size_t)NN * NH];
__device__ float g_wV[(size_t)NN * DIM];
__device__ float g_rowV[(size_t)NN * DIM];
__device__ float g_v1[(size_t)NN * DIM];
__device__ float g_v2[(size_t)NN * DIM];
__device__ float g_s1[2 * DIM];
__device__ float g_s2[2 * DIM];
__device__ float g_se[2 * DIM];
// bf16 hi/lo pairs
__device__ bf16 g_xhi[(size_t)NN * DIM],  g_xlo[(size_t)NN * DIM];
__device__ bf16 g_eahi[(size_t)NE * DIM], g_ealo[(size_t)NE * DIM];
__device__ bf16 g_ethi[(size_t)NE * DIM], g_etlo[(size_t)NE * DIM];
__device__ bf16 g_hatth[(size_t)NN * DIM], g_hattl[(size_t)NN * DIM];
__device__ bf16 g_hbnh[(size_t)NN * DIM],  g_hbnl[(size_t)NN * DIM];
__device__ bf16 g_h2ah[(size_t)NN * 2 * DIM], g_h2al[(size_t)NN * 2 * DIM];
__device__ bf16 g_wq_h[DIM * DIM], g_wq_l[DIM * DIM];
__device__ bf16 g_wk_h[DIM * DIM], g_wk_l[DIM * DIM];
__device__ bf16 g_wv_h[DIM * DIM], g_wv_l[DIM * DIM];
__device__ bf16 g_we_h[DIM * 2 * DIM], g_we_l[DIM * 2 * DIM];
__device__ bf16 g_woh_h[DIM * DIM], g_woh_l[DIM * DIM];
__device__ bf16 g_woe_h[DIM * DIM], g_woe_l[DIM * DIM];
__device__ bf16 g_w1_h[DIM * 2 * DIM], g_w1_l[DIM * 2 * DIM];
__device__ bf16 g_w2_h[2 * DIM * DIM], g_w2_l[2 * DIM * DIM];

static inline int cdiv(long long a, long long b) { return (int)((a + b - 1) / b); }

// ---------------- helpers ----------------
__device__ __forceinline__ uint32_t smem_u32(const void* p) {
    uint32_t a;
    asm("{ .reg .u64 t; cvta.to.shared.u64 t, %1; cvt.u32.u64 %0, t; }" : "=r"(a) : "l"(p));
    return a;
}
__device__ __forceinline__ void ldsm4(uint32_t (&r)[4], uint32_t addr) {
    asm volatile("ldmatrix.sync.aligned.m8n8.x4.shared.b16 {%0,%1,%2,%3}, [%4];"
                 : "=r"(r[0]), "=r"(r[1]), "=r"(r[2]), "=r"(r[3]) : "r"(addr));
}
__device__ __forceinline__ void ldsm4t(uint32_t (&r)[4], uint32_t addr) {
    asm volatile("ldmatrix.sync.aligned.m8n8.x4.trans.shared.b16 {%0,%1,%2,%3}, [%4];"
                 : "=r"(r[0]), "=r"(r[1]), "=r"(r[2]), "=r"(r[3]) : "r"(addr));
}
__device__ __forceinline__ void mma16816(float (&d)[4], const uint32_t (&a)[4], const uint32_t* b) {
    asm volatile("mma.sync.aligned.m16n8k16.row.col.f32.bf16.bf16.f32 "
                 "{%0,%1,%2,%3}, {%4,%5,%6,%7}, {%8,%9}, {%0,%1,%2,%3};"
                 : "+f"(d[0]), "+f"(d[1]), "+f"(d[2]), "+f"(d[3])
                 : "r"(a[0]), "r"(a[1]), "r"(a[2]), "r"(a[3]), "r"(b[0]), "r"(b[1]));
}
__device__ __forceinline__ uint32_t pack2(bf16 a, bf16 b) {
    return (uint32_t)__bfloat16_as_ushort(a) | ((uint32_t)__bfloat16_as_ushort(b) << 16);
}
__device__ __forceinline__ float2 up2(uint32_t u) {
    return make_float2(__bfloat162float(__ushort_as_bfloat16((unsigned short)(u & 0xffff))),
                       __bfloat162float(__ushort_as_bfloat16((unsigned short)(u >> 16))));
}
__device__ __forceinline__ void split4(float4 v, uint2& hi, uint2& lo) {
    bf16 hx = __float2bfloat16(v.x), hy = __float2bfloat16(v.y);
    bf16 hz = __float2bfloat16(v.z), hw = __float2bfloat16(v.w);
    hi = make_uint2(pack2(hx, hy), pack2(hz, hw));
    lo = make_uint2(pack2(__float2bfloat16(v.x - __bfloat162float(hx)),
                          __float2bfloat16(v.y - __bfloat162float(hy))),
                    pack2(__float2bfloat16(v.z - __bfloat162float(hz)),
                          __float2bfloat16(v.w - __bfloat162float(hw))));
}
__device__ __forceinline__ uint32_t packsplit(float a, float b, uint32_t& lo) {
    bf16 h0 = __float2bfloat16(a), h1 = __float2bfloat16(b);
    lo = pack2(__float2bfloat16(a - __bfloat162float(h0)),
               __float2bfloat16(b - __bfloat162float(h1)));
    return pack2(h0, h1);
}
__device__ __forceinline__ void cp16(uint32_t dst, const void* src, int sz) {
    asm volatile("cp.async.cg.shared.global [%0], [%1], 16, %2;" :: "r"(dst), "l"(src), "r"(sz));
}
#define CP_COMMIT() asm volatile("cp.async.commit_group;" ::: "memory")
#define CP_WAIT0()  asm volatile("cp.async.wait_group 0;" ::: "memory")
#define CP_WAIT1()  asm volatile("cp.async.wait_group 1;" ::: "memory")

__device__ __forceinline__ void atomicMaxF(float* addr, float v) {
    if (v >= 0.f) atomicMax((int*)addr, __float_as_int(v));
    else          atomicMin((unsigned int*)addr, __float_as_uint(v));
}
__device__ __forceinline__ void red4(float* p, float a, float b, float c, float d) {
    asm volatile("red.global.add.v4.f32 [%0], {%1,%2,%3,%4};"
                 :: "l"(p), "f"(a), "f"(b), "f"(c), "f"(d) : "memory");
}

// ---------------- bf16-pair GEMM core: 128x128 tile, 256 thr, 2-stage pipe ----
// smem per stage: A_hi 128x80B, A_lo, B_hi 32x272B, B_lo
#define STG    37888u
#define AHI_O  0u
#define ALO_O  10240u
#define BHI_O  20480u
#define BLO_O  29184u
#define SMB_TOTAL 75776

struct GemmCoreB {
    uint32_t sb;
    int tid, lid, wm, wn, m0, n0;
    float acc[4][4][4];

    __device__ __forceinline__ void init(uint8_t* smp, int bm, int bn) {
        sb = smem_u32(smp);
        tid = threadIdx.x; lid = tid & 31;
        int wid = tid >> 5;
        wm = wid >> 2; wn = wid & 3;
        m0 = bm * 128; n0 = bn * 128;
#pragma unroll
        for (int i = 0; i < 4; i++)
#pragma unroll
            for (int j = 0; j < 4; j++)
#pragma unroll
                for (int q = 0; q < 4; q++) acc[i][j][q] = 0.f;
    }
    __device__ __forceinline__ void stage(int buf, const bf16* Ahi, const bf16* Alo,
                                          const bf16* Whi, const bf16* Wlo,
                                          int M, int Ncols, int K, int kb) {
        uint32_t base = sb + (uint32_t)buf * STG;
#pragma unroll
        for (int i = 0; i < 2; i++) {
            int c = tid + i * 256;
            int row = c >> 2, gr = c & 3;
            bool ok = (m0 + row) < M;
            size_t go = (size_t)(ok ? m0 + row : 0) * K + kb + gr * 8;
            uint32_t d = base + (uint32_t)row * 80 + (uint32_t)gr * 16;
            cp16(d + AHI_O, Ahi + go, ok ? 16 : 0);
            cp16(d + ALO_O, Alo + go, ok ? 16 : 0);
        }
#pragma unroll
        for (int i = 0; i < 2; i++) {
            int c = tid + i * 256;
            int k = c >> 4, gr = c & 15;
            size_t go = (size_t)(kb + k) * Ncols + n0 + gr * 8;
            uint32_t d = base + (uint32_t)k * 272 + (uint32_t)gr * 16;
            cp16(d + BHI_O, Whi + go, 16);
            cp16(d + BLO_O, Wlo + go, 16);
        }
        CP_COMMIT();
    }
    __device__ __forceinline__ void compute(int buf) {
        uint32_t base = sb + (uint32_t)buf * STG;
#pragma unroll
        for (int ks = 0; ks < 32; ks += 16) {
            uint32_t bhi[4][2], blo[4][2];
            const uint32_t brow = (uint32_t)(ks + (lid & 15)) * 272 + (uint32_t)((lid >> 4) * 16);
#pragma unroll
            for (int p = 0; p < 2; p++) {
                uint32_t baddr = base + brow + (uint32_t)(wn * 32 + p * 16) * 2;
                uint32_t r[4];
                ldsm4t(r, baddr + BHI_O);
                bhi[2 * p][0] = r[0]; bhi[2 * p][1] = r[1];
                bhi[2 * p + 1][0] = r[2]; bhi[2 * p + 1][1] = r[3];
                ldsm4t(r, baddr + BLO_O);
                blo[2 * p][0] = r[0]; blo[2 * p][1] = r[1];
                blo[2 * p + 1][0] = r[2]; blo[2 * p + 1][1] = r[3];
            }
            const uint32_t arow = (uint32_t)(wm * 64 + (lid & 15)) * 80
                                + (uint32_t)ks * 2 + (uint32_t)(lid >> 4) * 16;
#pragma unroll
            for (int mt = 0; mt < 4; mt++) {
                uint32_t aaddr = base + arow + (uint32_t)mt * (16 * 80);
                uint32_t ahi4[4], alo4[4];
                ldsm4(ahi4, aaddr + AHI_O);
                ldsm4(alo4, aaddr + ALO_O);
#pragma unroll
                for (int nt = 0; nt < 4; nt++) {
                    mma16816(acc[mt][nt], ahi4, bhi[nt]);
                    mma16816(acc[mt][nt], ahi4, blo[nt]);
                    mma16816(acc[mt][nt], alo4, bhi[nt]);
                }
            }
        }
    }
    __device__ __forceinline__ void run(const bf16* Ahi, const bf16* Alo,
                                        const bf16* Whi, const bf16* Wlo,
                                        int M, int Ncols, int K) {
        const int nch = K >> 5;
        stage(0, Ahi, Alo, Whi, Wlo, M, Ncols, K, 0);
        if (nch > 1) stage(1, Ahi, Alo, Whi, Wlo, M, Ncols, K, 32);
        for (int i = 0; i < nch; i++) {
            if (i == nch - 1) { CP_WAIT0(); } else { CP_WAIT1(); }
            __syncthreads();
            compute(i & 1);
            if (i + 2 < nch) {
                __syncthreads();
                stage(i & 1, Ahi, Alo, Whi, Wlo, M, Ncols, K, (i + 2) * 32);
            }
        }
    }
};

// ---------------- generic GEMM: RESMODE 0=none 1=f32 2=bf16pair; OUT 0=f32 1=pair
template <int RESMODE, int OUTMODE, bool RELU>
__global__ void __launch_bounds__(256, 2)
mma_gemmB(const bf16* __restrict__ Ahi, const bf16* __restrict__ Alo,
          const bf16* __restrict__ Whi, const bf16* __restrict__ Wlo,
          const float* __restrict__ bias, const float* __restrict__ resf,
          const bf16* __restrict__ reshi, const bf16* __restrict__ reslo,
          float* __restrict__ Cf, bf16* __restrict__ Chi, bf16* __restrict__ Clo,
          int M, int Ncols, int K)
{
    extern __shared__ __align__(16) uint8_t sm[];
    GemmCoreB g;
    g.init(sm, blockIdx.x, blockIdx.y);
    g.run(Ahi, Alo, Whi, Wlo, M, Ncols, K);

    const int qr = g.lid >> 2, qc = (g.lid & 3) * 2;
#pragma unroll
    for (int mt = 0; mt < 4; mt++) {
#pragma unroll
        for (int nt = 0; nt < 4; nt++) {
            int col = g.n0 + g.wn * 32 + nt * 8 + qc;
            float b0 = bias[col], b1 = bias[col + 1];
#pragma unroll
            for (int half = 0; half < 2; half++) {
                int row = g.m0 + g.wm * 64 + mt * 16 + qr + half * 8;
                if (row >= M) continue;
                float o0 = g.acc[mt][nt][half * 2 + 0] + b0;
                float o1 = g.acc[mt][nt][half * 2 + 1] + b1;
                size_t off = (size_t)row * Ncols + col;
                if (RESMODE == 1) {
                    float2 rr = *(const float2*)(resf + off);
                    o0 += rr.x; o1 += rr.y;
                } else if (RESMODE == 2) {
                    float2 rh = up2(*(const uint32_t*)(reshi + off));
                    float2 rl = up2(*(const uint32_t*)(reslo + off));
                    o0 += rh.x + rl.x; o1 += rh.y + rl.y;
                }
                if (RELU) { o0 = fmaxf(o0, 0.f); o1 = fmaxf(o1, 0.f); }
                if (OUTMODE == 0) {
                    *(float2*)(Cf + off) = make_float2(o0, o1);
                } else {
                    uint32_t lw, hw = packsplit(o0, o1, lw);
                    *(uint32_t*)(Chi + off) = hw;
                    *(uint32_t*)(Clo + off) = lw;
                }
            }
        }
    }
}

// ---------------- fused QKV (grid.y selects weight) ----------------
__global__ void __launch_bounds__(256, 2)
qkv_gemm(const bf16* __restrict__ xhi, const bf16* __restrict__ xlo,
         const bf16* __restrict__ qh, const bf16* __restrict__ ql,
         const bf16* __restrict__ kh, const bf16* __restrict__ kl,
         const bf16* __restrict__ vh, const bf16* __restrict__ vl,
         const float* __restrict__ bq, const float* __restrict__ bk,
         const float* __restrict__ bv,
         float* __restrict__ Qo, float* __restrict__ Ko, float* __restrict__ Vo)
{
    extern __shared__ __align__(16) uint8_t sm[];
    const bf16* Whi = qh; const bf16* Wlo = ql;
    const float* bias = bq; float* C = Qo;
    if (blockIdx.y == 1) { Whi = kh; Wlo = kl; bias = bk; C = Ko; }
    else if (blockIdx.y == 2) { Whi = vh; Wlo = vl; bias = bv; C = Vo; }

    GemmCoreB g;
    g.init(sm, blockIdx.x, 0);
    g.run(xhi, xlo, Whi, Wlo, NN, 128, 128);

    const int qr = g.lid >> 2, qc = (g.lid & 3) * 2;
#pragma unroll
    for (int mt = 0; mt < 4; mt++) {
#pragma unroll
        for (int nt = 0; nt < 4; nt++) {
            int col = g.wn * 32 + nt * 8 + qc;
            float b0 = bias[col], b1 = bias[col + 1];
#pragma unroll
            for (int half = 0; half < 2; half++) {
                int row = g.m0 + g.wm * 64 + mt * 16 + qr + half * 8;
                if (row >= NN) continue;
                *(float2*)(C + (size_t)row * 128 + col) =
                    make_float2(g.acc[mt][nt][half * 2 + 0] + b0,
                                g.acc[mt][nt][half * 2 + 1] + b1);
            }
        }
    }
}

// ---------------- fused Ee GEMM + edge score/logit ----------------
union U16 { float4 q[4]; float f[16]; };

__global__ void __launch_bounds__(256, 2)
edge_gemm_fused(const bf16* __restrict__ eahi, const bf16* __restrict__ ealo,
                const bf16* __restrict__ weh, const bf16* __restrict__ wel,
                const float* __restrict__ bias,
                const int* __restrict__ ei, const float* __restrict__ Aw,
                const float* __restrict__ Qh, const float* __restrict__ Kh,
                bf16* __restrict__ ethi, bf16* __restrict__ etlo,
                float* __restrict__ lg, float* __restrict__ mx)
{
    extern __shared__ __align__(16) uint8_t sm[];
    __shared__ float sAw[DIM];
    if (threadIdx.x < DIM) sAw[threadIdx.x] = Aw[threadIdx.x];

    GemmCoreB g;
    g.init(sm, blockIdx.x, blockIdx.y);
    g.run(eahi, ealo, weh, wel, NE, 256, 128);

    __syncthreads();   // tiles dead; reuse smem for the output tile
    float* sC = (float*)sm;          // 128 rows x 132 pitch (67584B <= 75776)
    const int qr = g.lid >> 2, qc = (g.lid & 3) * 2;
#pragma unroll
    for (int mt = 0; mt < 4; mt++) {
#pragma unroll
        for (int nt = 0; nt < 4; nt++) {
            int col = g.wn * 32 + nt * 8 + qc;
            float b0 = bias[g.n0 + col], b1 = bias[g.n0 + col + 1];
#pragma unroll
            for (int half = 0; half < 2; half++) {
                int row = g.wm * 64 + mt * 16 + qr + half * 8;
                *(float2*)(sC + row * 132 + col) =
                    make_float2(g.acc[mt][nt][half * 2 + 0] + b0,
                                g.acc[mt][nt][half * 2 + 1] + b1);
            }
        }
    }
    __syncthreads();

    const int e = threadIdx.x & 127;
    const int ge = g.m0 + e;                    // NE % 128 == 0
    const int src = ei[ge], dst = ei[NE + ge];
#pragma unroll
    for (int u = 0; u < 2; u++) {
        const int hl = (threadIdx.x >> 7) * 2 + u;
        const int h = blockIdx.y * 4 + hl;
        const float* ew = sC + e * 132 + hl * 32;
        U16 K4, Q4, EW, EB, ET;
        const float4* kp = (const float4*)(Kh + (size_t)src * DIM + h * DH);
        const float4* qp = (const float4*)(Qh + (size_t)dst * DIM + h * DH);
#pragma unroll
        for (int q = 0; q < 4; q++) {
            K4.q[q] = kp[q]; Q4.q[q] = qp[q];
            EW.q[q] = *(const float4*)(ew + q * 4);
            EB.q[q] = *(const float4*)(ew + 16 + q * 4);
        }
        float logit = 0.f;
#pragma unroll
        for (int d = 0; d < 16; d++) {
            float s = (K4.f[d] + Q4.f[d]) * EW.f[d];
            float a = fabsf(s);
            float r = (a > 0.f) ? copysignf(sqrtf(a), s) : 0.f;
            float v = fmaxf(r + EB.f[d], 0.f);
            ET.f[d] = v;
            logit = fmaf(v, sAw[d * NH + h], logit);
        }
        logit = fminf(fmaxf(logit, -5.f), 5.f);
        // write et as bf16 hi/lo
        uint32_t hw[8], lw[8];
#pragma unroll
        for (int q = 0; q < 8; q++) hw[q] = packsplit(ET.f[2 * q], ET.f[2 * q + 1], lw[q]);
        bf16* ph = ethi + (size_t)ge * DIM + h * DH;
        bf16* pl = etlo + (size_t)ge * DIM + h * DH;
        *(uint4*)ph       = make_uint4(hw[0], hw[1], hw[2], hw[3]);
        *((uint4*)ph + 1) = make_uint4(hw[4], hw[5], hw[6], hw[7]);
        *(uint4*)pl       = make_uint4(lw[0], lw[1], lw[2], lw[3]);
        *((uint4*)pl + 1) = make_uint4(lw[4], lw[5], lw[6], lw[7]);
        lg[ge * NH + h] = logit;
        atomicMaxF(&mx[dst * NH + h], logit);
    }
}

// ---------------- misc / edge / node / bn kernels ----------------
__global__ void fill_kernel(float* p, float v, int n) {
    int i = blockIdx.x * blockDim.x + threadIdx.x;
    if (i < n) p[i] = v;
}

__global__ void preconv(const float* __restrict__ in, bf16* __restrict__ hi,
                        bf16* __restrict__ lo, long long n)
{
    long long i = ((long long)blockIdx.x * blockDim.x + threadIdx.x) * 4;
    if (i >= n) return;
    float4 v = *(const float4*)(in + i);
    uint2 h, l;
    split4(v, h, l);
    *(uint2*)(hi + i) = h;
    *(uint2*)(lo + i) = l;
}

__global__ void edge_pass2(const int* __restrict__ ei, float* __restrict__ lg,
                           const float* __restrict__ mx, float* __restrict__ den)
{
    int t = blockIdx.x * blockDim.x + threadIdx.x;
    if (t >= NE * NH) return;
    int e = t >> 3, h = t & 7;
    int dst = ei[NE + e];
    float ex = expf(lg[t] - mx[dst * NH + h]);
    lg[t] = ex;
    atomicAdd(&den[dst * NH + h], ex);
}

__global__ void edge_pass3(const int* __restrict__ ei, const float* __restrict__ lg,
                           const float* __restrict__ den, const float* __restrict__ Vh,
                           const bf16* __restrict__ ethi, const bf16* __restrict__ etlo,
                           float* __restrict__ wV, float* __restrict__ rowV)
{
    int t = blockIdx.x * blockDim.x + threadIdx.x;
    if (t >= NE * NH) return;
    int e = t >> 3, h = t & 7;
    int src = ei[e], dst = ei[NE + e];
    float attn = lg[t] / (den[dst * NH + h] + 1e-16f);
    U16 V4, E4;
    const float4* vp = (const float4*)(Vh + (size_t)src * DIM + h * DH);
#pragma unroll
    for (int q = 0; q < 4; q++) V4.q[q] = vp[q];
    const uint4* ph = (const uint4*)(ethi + (size_t)e * DIM + h * DH);
    const uint4* pl = (const uint4*)(etlo + (size_t)e * DIM + h * DH);
#pragma unroll
    for (int half = 0; half < 2; half++) {
        uint4 H = ph[half], L = pl[half];
        uint32_t hw[4] = {H.x, H.y, H.z, H.w}, lw[4] = {L.x, L.y, L.z, L.w};
#pragma unroll
        for (int q = 0; q < 4; q++) {
            float2 fh = up2(hw[q]), fl = up2(lw[q]);
            E4.f[half * 8 + q * 2 + 0] = fh.x + fl.x;
            E4.f[half * 8 + q * 2 + 1] = fh.y + fl.y;
        }
    }
    float* wv = wV + (size_t)dst * DIM + h * DH;
    float* rv = rowV + (size_t)dst * DIM + h * DH;
#pragma unroll
    for (int q = 0; q < 4; q++) {
        red4(wv + q * 4, V4.q[q].x * attn, V4.q[q].y * attn, V4.q[q].z * attn, V4.q[q].w * attn);
        red4(rv + q * 4, E4.f[q * 4] * attn, E4.f[q * 4 + 1] * attn,
             E4.f[q * 4 + 2] * attn, E4.f[q * 4 + 3] * attn);
    }
}

__global__ void node_fix(const float* __restrict__ wV, const float* __restrict__ rowV,
                         const float* __restrict__ VeRow, const float* __restrict__ log_deg,
                         const float* __restrict__ deg_coef,
                         bf16* __restrict__ hatth, bf16* __restrict__ hattl)
{
    int t = blockIdx.x * blockDim.x + threadIdx.x;
    if (t >= NN * 64) return;
    int n = t >> 6, c0 = (t & 63) * 2, h = c0 >> 4, co = c0 & 15;
    size_t off = (size_t)n * DIM + c0;
    float a0 = wV[off], a1 = wV[off + 1];
    const float* rv = rowV + (size_t)n * DIM + h * DH;
#pragma unroll
    for (int d2 = 0; d2 < 16; d2++) {
        float r = rv[d2];
        a0 = fmaf(r, VeRow[d2 * DIM + h * DH + co], a0);
        a1 = fmaf(r, VeRow[d2 * DIM + h * DH + co + 1], a1);
    }
    float ld = log_deg[n];
    float o0 = a0 * (deg_coef[2 * c0] + ld * deg_coef[2 * c0 + 1]);
    float o1 = a1 * (deg_coef[2 * c0 + 2] + ld * deg_coef[2 * c0 + 3]);
    uint32_t lw, hw = packsplit(o0, o1, lw);
    *(uint32_t*)(hatth + off) = hw;
    *(uint32_t*)(hattl + off) = lw;
}

__global__ void bn_stats(const float* __restrict__ v, int M, float* __restrict__ sums)
{
    int c = threadIdx.x;
    float s = 0.f, s2 = 0.f;
    for (int r = blockIdx.x; r < M; r += gridDim.x) {
        float x = v[(size_t)r * DIM + c];
        s += x;
        s2 = fmaf(x, x, s2);
    }
    atomicAdd(&sums[c], s);
    atomicAdd(&sums[DIM + c], s2);
}

template <bool PAIR>
__global__ void bn_apply(const float* __restrict__ v, float* __restrict__ outf,
                         bf16* __restrict__ outhi, bf16* __restrict__ outlo, int M,
                         const float* __restrict__ sums,
                         const float* __restrict__ g, const float* __restrict__ b, float invM)
{
    long long i = ((long long)blockIdx.x * blockDim.x + threadIdx.x) * 2;
    if (i >= (long long)M * DIM) return;
    int c = (int)(i & (DIM - 1));
    float m0 = sums[c] * invM, m1 = sums[c + 1] * invM;
    float var0 = fmaf(-m0, m0, sums[DIM + c] * invM);
    float var1 = fmaf(-m1, m1, sums[DIM + c + 1] * invM);
    float2 vv = *(const float2*)(v + i);
    float o0 = (vv.x - m0) * rsqrtf(var0 + 1e-5f) * g[c] + b[c];
    float o1 = (vv.y - m1) * rsqrtf(var1 + 1e-5f) * g[c + 1] + b[c + 1];
    if (!PAIR) {
        *(float2*)(outf + i) = make_float2(o0, o1);
    } else {
        uint32_t lw, hw = packsplit(o0, o1, lw);
        *(uint32_t*)(outhi + i) = hw;
        *(uint32_t*)(outlo + i) = lw;
    }
}

// ---------------- launch ----------------
#define SYM(var, sym) cudaGetSymbolAddress((void**)&var, sym)

extern "C" void kernel_launch(void* const* d_in, const int* in_sizes, int n_in,
                              void* d_out, int out_size)
{
    const float* x         = (const float*)d_in[0];
    const float* edge_attr = (const float*)d_in[1];
    const int*   ei        = (const int*)d_in[2];
    const float* log_deg   = (const float*)d_in[3];
    const float* Wq = (const float*)d_in[4],  *bq  = (const float*)d_in[5];
    const float* Wk = (const float*)d_in[6],  *bk  = (const float*)d_in[7];
    const float* We = (const float*)d_in[8],  *be  = (const float*)d_in[9];
    const float* Wv = (const float*)d_in[10], *bv  = (const float*)d_in[11];
    const float* Aw = (const float*)d_in[12], *VeRow = (const float*)d_in[13];
    const float* WOh = (const float*)d_in[14], *bOh = (const float*)d_in[15];
    const float* WOe = (const float*)d_in[16], *bOe = (const float*)d_in[17];
    const float* deg_coef = (const float*)d_in[18];
    const float* g1h = (const float*)d_in[19], *b1h = (const float*)d_in[20];
    const float* g1e = (const float*)d_in[21], *b1e = (const float*)d_in[22];
    const float* g2h = (const float*)d_in[23], *b2h = (const float*)d_in[24];
    const float* W1 = (const float*)d_in[25], *b1 = (const float*)d_in[26];
    const float* W2 = (const float*)d_in[27], *b2 = (const float*)d_in[28];

    float *Qh, *Kh, *Vh, *lg, *mx, *den, *wV, *rowV, *v1, *v2, *s1, *s2, *se;
    SYM(Qh, g_Qh); SYM(Kh, g_Kh); SYM(Vh, g_Vh);
    SYM(lg, g_lg); SYM(mx, g_mx); SYM(den, g_den);
    SYM(wV, g_wV); SYM(rowV, g_rowV);
    SYM(v1, g_v1); SYM(v2, g_v2);
    SYM(s1, g_s1); SYM(s2, g_s2); SYM(se, g_se);
    bf16 *xhi, *xlo, *eahi, *ealo, *ethi, *etlo, *hatth, *hattl, *hbnh, *hbnl, *h2ah, *h2al;
    SYM(xhi, g_xhi); SYM(xlo, g_xlo); SYM(eahi, g_eahi); SYM(ealo, g_ealo);
    SYM(ethi, g_ethi); SYM(etlo, g_etlo);
    SYM(hatth, g_hatth); SYM(hattl, g_hattl);
    SYM(hbnh, g_hbnh); SYM(hbnl, g_hbnl);
    SYM(h2ah, g_h2ah); SYM(h2al, g_h2al);
    bf16 *wq_h, *wq_l, *wk_h, *wk_l, *wv_h, *wv_l, *we_h, *we_l;
    bf16 *woh_h, *woh_l, *woe_h, *woe_l, *w1_h, *w1_l, *w2_h, *w2_l;
    SYM(wq_h, g_wq_h); SYM(wq_l, g_wq_l); SYM(wk_h, g_wk_h); SYM(wk_l, g_wk_l);
    SYM(wv_h, g_wv_h); SYM(wv_l, g_wv_l); SYM(we_h, g_we_h); SYM(we_l, g_we_l);
    SYM(woh_h, g_woh_h); SYM(woh_l, g_woh_l); SYM(woe_h, g_woe_h); SYM(woe_l, g_woe_l);
    SYM(w1_h, g_w1_h); SYM(w1_l, g_w1_l); SYM(w2_h, g_w2_h); SYM(w2_l, g_w2_l);

    float* hout = (float*)d_out;
    float* eout = (float*)d_out + (size_t)NN * DIM;

    cudaFuncSetAttribute(mma_gemmB<1, 0, false>, cudaFuncAttributeMaxDynamicSharedMemorySize, SMB_TOTAL);
    cudaFuncSetAttribute(mma_gemmB<0, 1, true >, cudaFuncAttributeMaxDynamicSharedMemorySize, SMB_TOTAL);
    cudaFuncSetAttribute(mma_gemmB<2, 0, false>, cudaFuncAttributeMaxDynamicSharedMemorySize, SMB_TOTAL);
    cudaFuncSetAttribute(qkv_gemm, cudaFuncAttributeMaxDynamicSharedMemorySize, SMB_TOTAL);
    cudaFuncSetAttribute(edge_gemm_fused, cudaFuncAttributeMaxDynamicSharedMemorySize, SMB_TOTAL);

    // ---- pre-convert fp32 -> bf16 hi/lo ----
    auto pc = [&](const float* in, bf16* h, bf16* l, long long n) {
        preconv<<<cdiv(n / 4, 256), 256>>>(in, h, l, n);
    };
    pc(x, xhi, xlo, (long long)NN * DIM);
    pc(edge_attr, eahi, ealo, (long long)NE * DIM);
    pc(Wq, wq_h, wq_l, DIM * DIM);
    pc(Wk, wk_h, wk_l, DIM * DIM);
    pc(Wv, wv_h, wv_l, DIM * DIM);
    pc(We, we_h, we_l, DIM * 2 * DIM);
    pc(WOh, woh_h, woh_l, DIM * DIM);
    pc(WOe, woe_h, woe_l, DIM * DIM);
    pc(W1, w1_h, w1_l, DIM * 2 * DIM);
    pc(W2, w2_h, w2_l, 2 * DIM * DIM);

    // init accumulators
    cudaMemsetAsync(wV, 0, (size_t)NN * DIM * sizeof(float));
    cudaMemsetAsync(rowV, 0, (size_t)NN * DIM * sizeof(float));
    cudaMemsetAsync(den, 0, (size_t)NN * NH * sizeof(float));
    cudaMemsetAsync(s1, 0, 2 * DIM * sizeof(float));
    cudaMemsetAsync(s2, 0, 2 * DIM * sizeof(float));
    cudaMemsetAsync(se, 0, 2 * DIM * sizeof(float));
    fill_kernel<<<cdiv(NN * NH, 256), 256>>>(mx, -1e30f, NN * NH);

    const int gN = cdiv(NN, 128), gE = cdiv(NE, 128);

    // Q/K/V in one launch
    qkv_gemm<<<dim3(gN, 3), 256, SMB_TOTAL>>>(xhi, xlo, wq_h, wq_l, wk_h, wk_l,
                                              wv_h, wv_l, bq, bk, bv, Qh, Kh, Vh);

    // fused Ee GEMM + score/logit/segment-max
    edge_gemm_fused<<<dim3(gE, 2), 256, SMB_TOTAL>>>(eahi, ealo, we_h, we_l, be,
                                                     ei, Aw, Qh, Kh, ethi, etlo, lg, mx);

    int eth = NE * NH;
    edge_pass2<<<cdiv(eth, 256), 256>>>(ei, lg, mx, den);
    edge_pass3<<<cdiv(eth, 256), 256>>>(ei, lg, den, Vh, ethi, etlo, wV, rowV);

    node_fix<<<cdiv(NN * 64, 256), 256>>>(wV, rowV, VeRow, log_deg, deg_coef, hatth, hattl);

    // h path: WOh + residual(x) -> v1; BN1 -> hbn pair
    mma_gemmB<1, 0, false><<<dim3(gN, 1), 256, SMB_TOTAL>>>(
        hatth, hattl, woh_h, woh_l, bOh, x, nullptr, nullptr, v1, nullptr, nullptr, NN, 128, 128);
    bn_stats<<<1024, 128>>>(v1, NN, s1);
    bn_apply<true><<<cdiv((long long)NN * 64, 256), 256>>>(v1, nullptr, hbnh, hbnl, NN, s1, g1h, b1h, 1.f / NN);

    // e path: WOe + residual(edge_attr) -> eout; BN
    mma_gemmB<1, 0, false><<<dim3(gE, 1), 256, SMB_TOTAL>>>(
        ethi, etlo, woe_h, woe_l, bOe, edge_attr, nullptr, nullptr, eout, nullptr, nullptr, NE, 128, 128);
    bn_stats<<<4096, 128>>>(eout, NE, se);
    bn_apply<false><<<cdiv((long long)NE * 64, 256), 256>>>(eout, eout, nullptr, nullptr, NE, se, g1e, b1e, 1.f / NE);

    // FFN: W1(relu) -> h2a pair; W2 + residual(hbn pair) -> v2; BN2 -> hout
    mma_gemmB<0, 1, true><<<dim3(gN, 2), 256, SMB_TOTAL>>>(
        hbnh, hbnl, w1_h, w1_l, b1, nullptr, nullptr, nullptr, nullptr, h2ah, h2al, NN, 256, 128);
    mma_gemmB<2, 0, false><<<dim3(gN, 1), 256, SMB_TOTAL>>>(
        h2ah, h2al, w2_h, w2_l, b2, nullptr, hbnh, hbnl, v2, nullptr, nullptr, NN, 128, 256);
    bn_stats<<<1024, 128>>>(v2, NN, s2);
    bn_apply<false><<<cdiv((long long)NN * 64, 256), 256>>>(v2, hout, nullptr, nullptr, NN, s2, g2h, b2h, 1.f / NN);
}

// round 7
// speedup vs baseline: 1.5192x; 1.1107x over previous
#include <cuda_runtime.h>
#include <cuda_bf16.h>
#include <math.h>
#include <stdint.h>

#define NN 40000
#define NE 640000
#define DIM 128
#define NH 8
#define DH 16

typedef __nv_bfloat16 bf16;

// ---------------- scratch (device globals: allocation-free) ----------------
__device__ float g_Qh[(size_t)NN * DIM];
__device__ float g_Kh[(size_t)NN * DIM];
__device__ float g_Vh[(size_t)NN * DIM];
__device__ float g_lg[(size_t)NE * NH];
__device__ float g_mx[(size_t)NN * NH];
__device__ float g_den[(size_t)NN * NH];
__device__ float g_wV[(size_t)NN * DIM];
__device__ float g_rowV[(size_t)NN * DIM];
__device__ float g_v1[(size_t)NN * DIM];
__device__ float g_v2[(size_t)NN * DIM];
__device__ float g_s1[2 * DIM];
__device__ float g_s2[2 * DIM];
__device__ float g_se[2 * DIM];
// bf16 hi/lo pairs
__device__ bf16 g_xhi[(size_t)NN * DIM],  g_xlo[(size_t)NN * DIM];
__device__ bf16 g_eahi[(size_t)NE * DIM], g_ealo[(size_t)NE * DIM];
__device__ bf16 g_ethi[(size_t)NE * DIM], g_etlo[(size_t)NE * DIM];
__device__ bf16 g_hatth[(size_t)NN * DIM], g_hattl[(size_t)NN * DIM];
__device__ bf16 g_hbnh[(size_t)NN * DIM],  g_hbnl[(size_t)NN * DIM];
__device__ bf16 g_h2ah[(size_t)NN * 2 * DIM], g_h2al[(size_t)NN * 2 * DIM];
__device__ bf16 g_wq_h[DIM * DIM], g_wq_l[DIM * DIM];
__device__ bf16 g_wk_h[DIM * DIM], g_wk_l[DIM * DIM];
__device__ bf16 g_wv_h[DIM * DIM], g_wv_l[DIM * DIM];
__device__ bf16 g_we_h[DIM * 2 * DIM], g_we_l[DIM * 2 * DIM];
__device__ bf16 g_woh_h[DIM * DIM], g_woh_l[DIM * DIM];
__device__ bf16 g_woe_h[DIM * DIM], g_woe_l[DIM * DIM];
__device__ bf16 g_w1_h[DIM * 2 * DIM], g_w1_l[DIM * 2 * DIM];
__device__ bf16 g_w2_h[2 * DIM * DIM], g_w2_l[2 * DIM * DIM];

static inline int cdiv(long long a, long long b) { return (int)((a + b - 1) / b); }

// ---------------- helpers ----------------
__device__ __forceinline__ uint32_t smem_u32(const void* p) {
    uint32_t a;
    asm("{ .reg .u64 t; cvta.to.shared.u64 t, %1; cvt.u32.u64 %0, t; }" : "=r"(a) : "l"(p));
    return a;
}
__device__ __forceinline__ void ldsm4(uint32_t (&r)[4], uint32_t addr) {
    asm volatile("ldmatrix.sync.aligned.m8n8.x4.shared.b16 {%0,%1,%2,%3}, [%4];"
                 : "=r"(r[0]), "=r"(r[1]), "=r"(r[2]), "=r"(r[3]) : "r"(addr));
}
__device__ __forceinline__ void ldsm4t(uint32_t (&r)[4], uint32_t addr) {
    asm volatile("ldmatrix.sync.aligned.m8n8.x4.trans.shared.b16 {%0,%1,%2,%3}, [%4];"
                 : "=r"(r[0]), "=r"(r[1]), "=r"(r[2]), "=r"(r[3]) : "r"(addr));
}
__device__ __forceinline__ void mma16816(float (&d)[4], const uint32_t (&a)[4], const uint32_t* b) {
    asm volatile("mma.sync.aligned.m16n8k16.row.col.f32.bf16.bf16.f32 "
                 "{%0,%1,%2,%3}, {%4,%5,%6,%7}, {%8,%9}, {%0,%1,%2,%3};"
                 : "+f"(d[0]), "+f"(d[1]), "+f"(d[2]), "+f"(d[3])
                 : "r"(a[0]), "r"(a[1]), "r"(a[2]), "r"(a[3]), "r"(b[0]), "r"(b[1]));
}
__device__ __forceinline__ uint32_t pack2(bf16 a, bf16 b) {
    return (uint32_t)__bfloat16_as_ushort(a) | ((uint32_t)__bfloat16_as_ushort(b) << 16);
}
__device__ __forceinline__ float2 up2(uint32_t u) {
    return make_float2(__bfloat162float(__ushort_as_bfloat16((unsigned short)(u & 0xffff))),
                       __bfloat162float(__ushort_as_bfloat16((unsigned short)(u >> 16))));
}
__device__ __forceinline__ void split4(float4 v, uint2& hi, uint2& lo) {
    bf16 hx = __float2bfloat16(v.x), hy = __float2bfloat16(v.y);
    bf16 hz = __float2bfloat16(v.z), hw = __float2bfloat16(v.w);
    hi = make_uint2(pack2(hx, hy), pack2(hz, hw));
    lo = make_uint2(pack2(__float2bfloat16(v.x - __bfloat162float(hx)),
                          __float2bfloat16(v.y - __bfloat162float(hy))),
                    pack2(__float2bfloat16(v.z - __bfloat162float(hz)),
                          __float2bfloat16(v.w - __bfloat162float(hw))));
}
__device__ __forceinline__ uint32_t packsplit(float a, float b, uint32_t& lo) {
    bf16 h0 = __float2bfloat16(a), h1 = __float2bfloat16(b);
    lo = pack2(__float2bfloat16(a - __bfloat162float(h0)),
               __float2bfloat16(b - __bfloat162float(h1)));
    return pack2(h0, h1);
}
__device__ __forceinline__ void cp16(uint32_t dst, const void* src, int sz) {
    asm volatile("cp.async.cg.shared.global [%0], [%1], 16, %2;" :: "r"(dst), "l"(src), "r"(sz));
}
#define CP_COMMIT() asm volatile("cp.async.commit_group;" ::: "memory")
#define CP_WAIT0()  asm volatile("cp.async.wait_group 0;" ::: "memory")
#define CP_WAIT1()  asm volatile("cp.async.wait_group 1;" ::: "memory")

__device__ __forceinline__ void atomicMaxF(float* addr, float v) {
    if (v >= 0.f) atomicMax((int*)addr, __float_as_int(v));
    else          atomicMin((unsigned int*)addr, __float_as_uint(v));
}
__device__ __forceinline__ void red4(float* p, float a, float b, float c, float d) {
    asm volatile("red.global.add.v4.f32 [%0], {%1,%2,%3,%4};"
                 :: "l"(p), "f"(a), "f"(b), "f"(c), "f"(d) : "memory");
}
__device__ __forceinline__ void redf(float* p, float a) {
    asm volatile("red.global.add.f32 [%0], %1;" :: "l"(p), "f"(a) : "memory");
}

// ---------------- bf16-pair GEMM core: 128x128 tile, 256 thr, 2-stage pipe ----
#define STG    37888u
#define AHI_O  0u
#define ALO_O  10240u
#define BHI_O  20480u
#define BLO_O  29184u
#define SMB_TOTAL 75776

struct GemmCoreB {
    uint32_t sb;
    int tid, lid, wm, wn, m0, n0;
    float acc[4][4][4];

    __device__ __forceinline__ void init(uint8_t* smp, int bm, int bn) {
        sb = smem_u32(smp);
        tid = threadIdx.x; lid = tid & 31;
        int wid = tid >> 5;
        wm = wid >> 2; wn = wid & 3;
        m0 = bm * 128; n0 = bn * 128;
#pragma unroll
        for (int i = 0; i < 4; i++)
#pragma unroll
            for (int j = 0; j < 4; j++)
#pragma unroll
                for (int q = 0; q < 4; q++) acc[i][j][q] = 0.f;
    }
    __device__ __forceinline__ void stage(int buf, const bf16* Ahi, const bf16* Alo,
                                          const bf16* Whi, const bf16* Wlo,
                                          int M, int Ncols, int K, int kb) {
        uint32_t base = sb + (uint32_t)buf * STG;
#pragma unroll
        for (int i = 0; i < 2; i++) {
            int c = tid + i * 256;
            int row = c >> 2, gr = c & 3;
            bool ok = (m0 + row) < M;
            size_t go = (size_t)(ok ? m0 + row : 0) * K + kb + gr * 8;
            uint32_t d = base + (uint32_t)row * 80 + (uint32_t)gr * 16;
            cp16(d + AHI_O, Ahi + go, ok ? 16 : 0);
            cp16(d + ALO_O, Alo + go, ok ? 16 : 0);
        }
#pragma unroll
        for (int i = 0; i < 2; i++) {
            int c = tid + i * 256;
            int k = c >> 4, gr = c & 15;
            size_t go = (size_t)(kb + k) * Ncols + n0 + gr * 8;
            uint32_t d = base + (uint32_t)k * 272 + (uint32_t)gr * 16;
            cp16(d + BHI_O, Whi + go, 16);
            cp16(d + BLO_O, Wlo + go, 16);
        }
        CP_COMMIT();
    }
    __device__ __forceinline__ void compute(int buf) {
        uint32_t base = sb + (uint32_t)buf * STG;
#pragma unroll
        for (int ks = 0; ks < 32; ks += 16) {
            uint32_t bhi[4][2], blo[4][2];
            const uint32_t brow = (uint32_t)(ks + (lid & 15)) * 272 + (uint32_t)((lid >> 4) * 16);
#pragma unroll
            for (int p = 0; p < 2; p++) {
                uint32_t baddr = base + brow + (uint32_t)(wn * 32 + p * 16) * 2;
                uint32_t r[4];
                ldsm4t(r, baddr + BHI_O);
                bhi[2 * p][0] = r[0]; bhi[2 * p][1] = r[1];
                bhi[2 * p + 1][0] = r[2]; bhi[2 * p + 1][1] = r[3];
                ldsm4t(r, baddr + BLO_O);
                blo[2 * p][0] = r[0]; blo[2 * p][1] = r[1];
                blo[2 * p + 1][0] = r[2]; blo[2 * p + 1][1] = r[3];
            }
            const uint32_t arow = (uint32_t)(wm * 64 + (lid & 15)) * 80
                                + (uint32_t)ks * 2 + (uint32_t)(lid >> 4) * 16;
#pragma unroll
            for (int mt = 0; mt < 4; mt++) {
                uint32_t aaddr = base + arow + (uint32_t)mt * (16 * 80);
                uint32_t ahi4[4], alo4[4];
                ldsm4(ahi4, aaddr + AHI_O);
                ldsm4(alo4, aaddr + ALO_O);
#pragma unroll
                for (int nt = 0; nt < 4; nt++) {
                    mma16816(acc[mt][nt], ahi4, bhi[nt]);
                    mma16816(acc[mt][nt], ahi4, blo[nt]);
                    mma16816(acc[mt][nt], alo4, bhi[nt]);
                }
            }
        }
    }
    __device__ __forceinline__ void run(const bf16* Ahi, const bf16* Alo,
                                        const bf16* Whi, const bf16* Wlo,
                                        int M, int Ncols, int K) {
        const int nch = K >> 5;
        stage(0, Ahi, Alo, Whi, Wlo, M, Ncols, K, 0);
        if (nch > 1) stage(1, Ahi, Alo, Whi, Wlo, M, Ncols, K, 32);
        for (int i = 0; i < nch; i++) {
            if (i == nch - 1) { CP_WAIT0(); } else { CP_WAIT1(); }
            __syncthreads();
            compute(i & 1);
            if (i + 2 < nch) {
                __syncthreads();
                stage(i & 1, Ahi, Alo, Whi, Wlo, M, Ncols, K, (i + 2) * 32);
            }
        }
    }
};

// ---------------- generic GEMM (m-tile = blockIdx.y, n-tile = blockIdx.x) ----
// RESMODE 0=none 1=f32 2=bf16pair; OUTMODE 0=f32 1=pair; STATS: fused col sums
template <int RESMODE, int OUTMODE, bool RELU, bool STATS>
__global__ void __launch_bounds__(256, 2)
mma_gemmB(const bf16* __restrict__ Ahi, const bf16* __restrict__ Alo,
          const bf16* __restrict__ Whi, const bf16* __restrict__ Wlo,
          const float* __restrict__ bias, const float* __restrict__ resf,
          const bf16* __restrict__ reshi, const bf16* __restrict__ reslo,
          float* __restrict__ Cf, bf16* __restrict__ Chi, bf16* __restrict__ Clo,
          float* __restrict__ stats, int M, int Ncols, int K)
{
    extern __shared__ __align__(16) uint8_t sm[];
    GemmCoreB g;
    g.init(sm, blockIdx.y, blockIdx.x);
    g.run(Ahi, Alo, Whi, Wlo, M, Ncols, K);

    float ts0[4], ts1[4], tq0[4], tq1[4];
    if (STATS) {
#pragma unroll
        for (int nt = 0; nt < 4; nt++) { ts0[nt] = ts1[nt] = tq0[nt] = tq1[nt] = 0.f; }
    }

    const int qr = g.lid >> 2, qc = (g.lid & 3) * 2;
#pragma unroll
    for (int mt = 0; mt < 4; mt++) {
#pragma unroll
        for (int nt = 0; nt < 4; nt++) {
            int col = g.n0 + g.wn * 32 + nt * 8 + qc;
            float b0 = bias[col], b1 = bias[col + 1];
#pragma unroll
            for (int half = 0; half < 2; half++) {
                int row = g.m0 + g.wm * 64 + mt * 16 + qr + half * 8;
                if (row >= M) continue;
                float o0 = g.acc[mt][nt][half * 2 + 0] + b0;
                float o1 = g.acc[mt][nt][half * 2 + 1] + b1;
                size_t off = (size_t)row * Ncols + col;
                if (RESMODE == 1) {
                    float2 rr = *(const float2*)(resf + off);
                    o0 += rr.x; o1 += rr.y;
                } else if (RESMODE == 2) {
                    float2 rh = up2(*(const uint32_t*)(reshi + off));
                    float2 rl = up2(*(const uint32_t*)(reslo + off));
                    o0 += rh.x + rl.x; o1 += rh.y + rl.y;
                }
                if (RELU) { o0 = fmaxf(o0, 0.f); o1 = fmaxf(o1, 0.f); }
                if (STATS) {
                    ts0[nt] += o0; ts1[nt] += o1;
                    tq0[nt] = fmaf(o0, o0, tq0[nt]); tq1[nt] = fmaf(o1, o1, tq1[nt]);
                }
                if (OUTMODE == 0) {
                    *(float2*)(Cf + off) = make_float2(o0, o1);
                } else {
                    uint32_t lw, hw = packsplit(o0, o1, lw);
                    *(uint32_t*)(Chi + off) = hw;
                    *(uint32_t*)(Clo + off) = lw;
                }
            }
        }
    }
    if (STATS) {
#pragma unroll
        for (int nt = 0; nt < 4; nt++) {
            float a = ts0[nt], b = ts1[nt], c = tq0[nt], d = tq1[nt];
#pragma unroll
            for (int m = 4; m <= 16; m <<= 1) {
                a += __shfl_xor_sync(0xffffffff, a, m);
                b += __shfl_xor_sync(0xffffffff, b, m);
                c += __shfl_xor_sync(0xffffffff, c, m);
                d += __shfl_xor_sync(0xffffffff, d, m);
            }
            if (qr == 0) {
                int col = g.n0 + g.wn * 32 + nt * 8 + qc;
                redf(stats + col, a);
                redf(stats + col + 1, b);
                redf(stats + DIM + col, c);
                redf(stats + DIM + col + 1, d);
            }
        }
    }
}

// ---------------- fused QKV (blockIdx.x selects weight, y = m tile) ----------
__global__ void __launch_bounds__(256, 2)
qkv_gemm(const bf16* __restrict__ xhi, const bf16* __restrict__ xlo,
         const bf16* __restrict__ qh, const bf16* __restrict__ ql,
         const bf16* __restrict__ kh, const bf16* __restrict__ kl,
         const bf16* __restrict__ vh, const bf16* __restrict__ vl,
         const float* __restrict__ bq, const float* __restrict__ bk,
         const float* __restrict__ bv,
         float* __restrict__ Qo, float* __restrict__ Ko, float* __restrict__ Vo)
{
    extern __shared__ __align__(16) uint8_t sm[];
    const bf16* Whi = qh; const bf16* Wlo = ql;
    const float* bias = bq; float* C = Qo;
    if (blockIdx.x == 1) { Whi = kh; Wlo = kl; bias = bk; C = Ko; }
    else if (blockIdx.x == 2) { Whi = vh; Wlo = vl; bias = bv; C = Vo; }

    GemmCoreB g;
    g.init(sm, blockIdx.y, 0);
    g.run(xhi, xlo, Whi, Wlo, NN, 128, 128);

    const int qr = g.lid >> 2, qc = (g.lid & 3) * 2;
#pragma unroll
    for (int mt = 0; mt < 4; mt++) {
#pragma unroll
        for (int nt = 0; nt < 4; nt++) {
            int col = g.wn * 32 + nt * 8 + qc;
            float b0 = bias[col], b1 = bias[col + 1];
#pragma unroll
            for (int half = 0; half < 2; half++) {
                int row = g.m0 + g.wm * 64 + mt * 16 + qr + half * 8;
                if (row >= NN) continue;
                *(float2*)(C + (size_t)row * 128 + col) =
                    make_float2(g.acc[mt][nt][half * 2 + 0] + b0,
                                g.acc[mt][nt][half * 2 + 1] + b1);
            }
        }
    }
}

// ---------------- fused Ee GEMM + edge score/logit ----------------
// grid (2, gE): blockIdx.x = head-half (n-tile), blockIdx.y = edge tile.
union U16 { float4 q[4]; float f[16]; };

__global__ void __launch_bounds__(256, 2)
edge_gemm_fused(const bf16* __restrict__ eahi, const bf16* __restrict__ ealo,
                const bf16* __restrict__ weh, const bf16* __restrict__ wel,
                const float* __restrict__ bias,
                const int* __restrict__ ei, const float* __restrict__ Aw,
                const float* __restrict__ Qh, const float* __restrict__ Kh,
                bf16* __restrict__ ethi, bf16* __restrict__ etlo,
                float* __restrict__ lg, float* __restrict__ mx)
{
    extern __shared__ __align__(16) uint8_t sm[];
    __shared__ float sAw[DIM];
    if (threadIdx.x < DIM) sAw[threadIdx.x] = Aw[threadIdx.x];

    GemmCoreB g;
    g.init(sm, blockIdx.y, blockIdx.x);
    g.run(eahi, ealo, weh, wel, NE, 256, 128);

    __syncthreads();   // tiles dead; reuse smem for the output tile
    float* sC = (float*)sm;          // 128 rows x 132 pitch
    const int qr = g.lid >> 2, qc = (g.lid & 3) * 2;
#pragma unroll
    for (int mt = 0; mt < 4; mt++) {
#pragma unroll
        for (int nt = 0; nt < 4; nt++) {
            int col = g.wn * 32 + nt * 8 + qc;
            float b0 = bias[g.n0 + col], b1 = bias[g.n0 + col + 1];
#pragma unroll
            for (int half = 0; half < 2; half++) {
                int row = g.wm * 64 + mt * 16 + qr + half * 8;
                *(float2*)(sC + row * 132 + col) =
                    make_float2(g.acc[mt][nt][half * 2 + 0] + b0,
                                g.acc[mt][nt][half * 2 + 1] + b1);
            }
        }
    }
    __syncthreads();

    const int e = threadIdx.x & 127;
    const int ge = g.m0 + e;                    // NE % 128 == 0
    const int src = ei[ge], dst = ei[NE + ge];
#pragma unroll
    for (int u = 0; u < 2; u++) {
        const int hl = (threadIdx.x >> 7) * 2 + u;
        const int h = blockIdx.x * 4 + hl;
        const float* ew = sC + e * 132 + hl * 32;
        U16 K4, Q4, EW, EB, ET;
        const float4* kp = (const float4*)(Kh + (size_t)src * DIM + h * DH);
        const float4* qp = (const float4*)(Qh + (size_t)dst * DIM + h * DH);
#pragma unroll
        for (int q = 0; q < 4; q++) {
            K4.q[q] = kp[q]; Q4.q[q] = qp[q];
            EW.q[q] = *(const float4*)(ew + q * 4);
            EB.q[q] = *(const float4*)(ew + 16 + q * 4);
        }
        float logit = 0.f;
#pragma unroll
        for (int d = 0; d < 16; d++) {
            float s = (K4.f[d] + Q4.f[d]) * EW.f[d];
            float a = fabsf(s);
            float r = (a > 0.f) ? copysignf(sqrtf(a), s) : 0.f;
            float v = fmaxf(r + EB.f[d], 0.f);
            ET.f[d] = v;
            logit = fmaf(v, sAw[d * NH + h], logit);
        }
        logit = fminf(fmaxf(logit, -5.f), 5.f);
        uint32_t hw[8], lw[8];
#pragma unroll
        for (int q = 0; q < 8; q++) hw[q] = packsplit(ET.f[2 * q], ET.f[2 * q + 1], lw[q]);
        bf16* ph = ethi + (size_t)ge * DIM + h * DH;
        bf16* pl = etlo + (size_t)ge * DIM + h * DH;
        *(uint4*)ph       = make_uint4(hw[0], hw[1], hw[2], hw[3]);
        *((uint4*)ph + 1) = make_uint4(hw[4], hw[5], hw[6], hw[7]);
        *(uint4*)pl       = make_uint4(lw[0], lw[1], lw[2], lw[3]);
        *((uint4*)pl + 1) = make_uint4(lw[4], lw[5], lw[6], lw[7]);
        lg[ge * NH + h] = logit;
        atomicMaxF(&mx[dst * NH + h], logit);
    }
}

// ---------------- misc / edge / node / bn kernels ----------------
__global__ void fill_kernel(float* p, float v, int n) {
    int i = blockIdx.x * blockDim.x + threadIdx.x;
    if (i < n) p[i] = v;
}

__global__ void preconv(const float* __restrict__ in, bf16* __restrict__ hi,
                        bf16* __restrict__ lo, long long n)
{
    long long i = ((long long)blockIdx.x * blockDim.x + threadIdx.x) * 4;
    if (i >= n) return;
    float4 v = *(const float4*)(in + i);
    uint2 h, l;
    split4(v, h, l);
    *(uint2*)(hi + i) = h;
    *(uint2*)(lo + i) = l;
}

// merged softmax-denominator + unnormalized scatter (normalize in node_fix)
__global__ void edge_pass23(const int* __restrict__ ei, const float* __restrict__ lg,
                            const float* __restrict__ mx, float* __restrict__ den,
                            const float* __restrict__ Vh,
                            const bf16* __restrict__ ethi, const bf16* __restrict__ etlo,
                            float* __restrict__ wV, float* __restrict__ rowV)
{
    int t = blockIdx.x * blockDim.x + threadIdx.x;
    if (t >= NE * NH) return;
    int e = t >> 3, h = t & 7;
    int src = ei[e], dst = ei[NE + e];
    float ex = expf(lg[t] - mx[dst * NH + h]);
    redf(&den[dst * NH + h], ex);
    U16 V4, E4;
    const float4* vp = (const float4*)(Vh + (size_t)src * DIM + h * DH);
#pragma unroll
    for (int q = 0; q < 4; q++) V4.q[q] = vp[q];
    const uint4* ph = (const uint4*)(ethi + (size_t)e * DIM + h * DH);
    const uint4* pl = (const uint4*)(etlo + (size_t)e * DIM + h * DH);
#pragma unroll
    for (int half = 0; half < 2; half++) {
        uint4 H = ph[half], L = pl[half];
        uint32_t hw[4] = {H.x, H.y, H.z, H.w}, lw[4] = {L.x, L.y, L.z, L.w};
#pragma unroll
        for (int q = 0; q < 4; q++) {
            float2 fh = up2(hw[q]), fl = up2(lw[q]);
            E4.f[half * 8 + q * 2 + 0] = fh.x + fl.x;
            E4.f[half * 8 + q * 2 + 1] = fh.y + fl.y;
        }
    }
    float* wv = wV + (size_t)dst * DIM + h * DH;
    float* rv = rowV + (size_t)dst * DIM + h * DH;
#pragma unroll
    for (int q = 0; q < 4; q++) {
        red4(wv + q * 4, V4.q[q].x * ex, V4.q[q].y * ex, V4.q[q].z * ex, V4.q[q].w * ex);
        red4(rv + q * 4, E4.f[q * 4] * ex, E4.f[q * 4 + 1] * ex,
             E4.f[q * 4 + 2] * ex, E4.f[q * 4 + 3] * ex);
    }
}

__global__ void node_fix(const float* __restrict__ wV, const float* __restrict__ rowV,
                         const float* __restrict__ den,
                         const float* __restrict__ VeRow, const float* __restrict__ log_deg,
                         const float* __restrict__ deg_coef,
                         bf16* __restrict__ hatth, bf16* __restrict__ hattl)
{
    int t = blockIdx.x * blockDim.x + threadIdx.x;
    if (t >= NN * 64) return;
    int n = t >> 6, c0 = (t & 63) * 2, h = c0 >> 4, co = c0 & 15;
    size_t off = (size_t)n * DIM + c0;
    float inv = 1.f / (den[n * NH + h] + 1e-16f);
    float a0 = wV[off], a1 = wV[off + 1];
    const float* rv = rowV + (size_t)n * DIM + h * DH;
#pragma unroll
    for (int d2 = 0; d2 < 16; d2++) {
        float r = rv[d2];
        a0 = fmaf(r, VeRow[d2 * DIM + h * DH + co], a0);
        a1 = fmaf(r, VeRow[d2 * DIM + h * DH + co + 1], a1);
    }
    a0 *= inv; a1 *= inv;
    float ld = log_deg[n];
    float o0 = a0 * (deg_coef[2 * c0] + ld * deg_coef[2 * c0 + 1]);
    float o1 = a1 * (deg_coef[2 * c0 + 2] + ld * deg_coef[2 * c0 + 3]);
    uint32_t lw, hw = packsplit(o0, o1, lw);
    *(uint32_t*)(hatth + off) = hw;
    *(uint32_t*)(hattl + off) = lw;
}

__global__ void bn_stats(const float* __restrict__ v, int M, float* __restrict__ sums)
{
    int c = threadIdx.x;
    float s = 0.f, s2 = 0.f;
    for (int r = blockIdx.x; r < M; r += gridDim.x) {
        float x = v[(size_t)r * DIM + c];
        s += x;
        s2 = fmaf(x, x, s2);
    }
    atomicAdd(&sums[c], s);
    atomicAdd(&sums[DIM + c], s2);
}

template <bool PAIR>
__global__ void bn_apply(const float* __restrict__ v, float* __restrict__ outf,
                         bf16* __restrict__ outhi, bf16* __restrict__ outlo, int M,
                         const float* __restrict__ sums,
                         const float* __restrict__ g, const float* __restrict__ b, float invM)
{
    long long i = ((long long)blockIdx.x * blockDim.x + threadIdx.x) * 2;
    if (i >= (long long)M * DIM) return;
    int c = (int)(i & (DIM - 1));
    float m0 = sums[c] * invM, m1 = sums[c + 1] * invM;
    float var0 = fmaf(-m0, m0, sums[DIM + c] * invM);
    float var1 = fmaf(-m1, m1, sums[DIM + c + 1] * invM);
    float2 vv = *(const float2*)(v + i);
    float o0 = (vv.x - m0) * rsqrtf(var0 + 1e-5f) * g[c] + b[c];
    float o1 = (vv.y - m1) * rsqrtf(var1 + 1e-5f) * g[c + 1] + b[c + 1];
    if (!PAIR) {
        *(float2*)(outf + i) = make_float2(o0, o1);
    } else {
        uint32_t lw, hw = packsplit(o0, o1, lw);
        *(uint32_t*)(outhi + i) = hw;
        *(uint32_t*)(outlo + i) = lw;
    }
}

// ---------------- launch ----------------
#define SYM(var, sym) cudaGetSymbolAddress((void**)&var, sym)

extern "C" void kernel_launch(void* const* d_in, const int* in_sizes, int n_in,
                              void* d_out, int out_size)
{
    const float* x         = (const float*)d_in[0];
    const float* edge_attr = (const float*)d_in[1];
    const int*   ei        = (const int*)d_in[2];
    const float* log_deg   = (const float*)d_in[3];
    const float* Wq = (const float*)d_in[4],  *bq  = (const float*)d_in[5];
    const float* Wk = (const float*)d_in[6],  *bk  = (const float*)d_in[7];
    const float* We = (const float*)d_in[8],  *be  = (const float*)d_in[9];
    const float* Wv = (const float*)d_in[10], *bv  = (const float*)d_in[11];
    const float* Aw = (const float*)d_in[12], *VeRow = (const float*)d_in[13];
    const float* WOh = (const float*)d_in[14], *bOh = (const float*)d_in[15];
    const float* WOe = (const float*)d_in[16], *bOe = (const float*)d_in[17];
    const float* deg_coef = (const float*)d_in[18];
    const float* g1h = (const float*)d_in[19], *b1h = (const float*)d_in[20];
    const float* g1e = (const float*)d_in[21], *b1e = (const float*)d_in[22];
    const float* g2h = (const float*)d_in[23], *b2h = (const float*)d_in[24];
    const float* W1 = (const float*)d_in[25], *b1 = (const float*)d_in[26];
    const float* W2 = (const float*)d_in[27], *b2 = (const float*)d_in[28];

    float *Qh, *Kh, *Vh, *lg, *mx, *den, *wV, *rowV, *v1, *v2, *s1, *s2, *se;
    SYM(Qh, g_Qh); SYM(Kh, g_Kh); SYM(Vh, g_Vh);
    SYM(lg, g_lg); SYM(mx, g_mx); SYM(den, g_den);
    SYM(wV, g_wV); SYM(rowV, g_rowV);
    SYM(v1, g_v1); SYM(v2, g_v2);
    SYM(s1, g_s1); SYM(s2, g_s2); SYM(se, g_se);
    bf16 *xhi, *xlo, *eahi, *ealo, *ethi, *etlo, *hatth, *hattl, *hbnh, *hbnl, *h2ah, *h2al;
    SYM(xhi, g_xhi); SYM(xlo, g_xlo); SYM(eahi, g_eahi); SYM(ealo, g_ealo);
    SYM(ethi, g_ethi); SYM(etlo, g_etlo);
    SYM(hatth, g_hatth); SYM(hattl, g_hattl);
    SYM(hbnh, g_hbnh); SYM(hbnl, g_hbnl);
    SYM(h2ah, g_h2ah); SYM(h2al, g_h2al);
    bf16 *wq_h, *wq_l, *wk_h, *wk_l, *wv_h, *wv_l, *we_h, *we_l;
    bf16 *woh_h, *woh_l, *woe_h, *woe_l, *w1_h, *w1_l, *w2_h, *w2_l;
    SYM(wq_h, g_wq_h); SYM(wq_l, g_wq_l); SYM(wk_h, g_wk_h); SYM(wk_l, g_wk_l);
    SYM(wv_h, g_wv_h); SYM(wv_l, g_wv_l); SYM(we_h, g_we_h); SYM(we_l, g_we_l);
    SYM(woh_h, g_woh_h); SYM(woh_l, g_woh_l); SYM(woe_h, g_woe_h); SYM(woe_l, g_woe_l);
    SYM(w1_h, g_w1_h); SYM(w1_l, g_w1_l); SYM(w2_h, g_w2_h); SYM(w2_l, g_w2_l);

    float* hout = (float*)d_out;
    float* eout = (float*)d_out + (size_t)NN * DIM;

    cudaFuncSetAttribute(mma_gemmB<1, 0, false, false>, cudaFuncAttributeMaxDynamicSharedMemorySize, SMB_TOTAL);
    cudaFuncSetAttribute(mma_gemmB<1, 0, false, true >, cudaFuncAttributeMaxDynamicSharedMemorySize, SMB_TOTAL);
    cudaFuncSetAttribute(mma_gemmB<0, 1, true,  false>, cudaFuncAttributeMaxDynamicSharedMemorySize, SMB_TOTAL);
    cudaFuncSetAttribute(mma_gemmB<2, 0, false, false>, cudaFuncAttributeMaxDynamicSharedMemorySize, SMB_TOTAL);
    cudaFuncSetAttribute(qkv_gemm, cudaFuncAttributeMaxDynamicSharedMemorySize, SMB_TOTAL);
    cudaFuncSetAttribute(edge_gemm_fused, cudaFuncAttributeMaxDynamicSharedMemorySize, SMB_TOTAL);

    // ---- pre-convert fp32 -> bf16 hi/lo ----
    auto pc = [&](const float* in, bf16* h, bf16* l, long long n) {
        preconv<<<cdiv(n / 4, 256), 256>>>(in, h, l, n);
    };
    pc(x, xhi, xlo, (long long)NN * DIM);
    pc(edge_attr, eahi, ealo, (long long)NE * DIM);
    pc(Wq, wq_h, wq_l, DIM * DIM);
    pc(Wk, wk_h, wk_l, DIM * DIM);
    pc(Wv, wv_h, wv_l, DIM * DIM);
    pc(We, we_h, we_l, DIM * 2 * DIM);
    pc(WOh, woh_h, woh_l, DIM * DIM);
    pc(WOe, woe_h, woe_l, DIM * DIM);
    pc(W1, w1_h, w1_l, DIM * 2 * DIM);
    pc(W2, w2_h, w2_l, 2 * DIM * DIM);

    // init accumulators
    cudaMemsetAsync(wV, 0, (size_t)NN * DIM * sizeof(float));
    cudaMemsetAsync(rowV, 0, (size_t)NN * DIM * sizeof(float));
    cudaMemsetAsync(den, 0, (size_t)NN * NH * sizeof(float));
    cudaMemsetAsync(s1, 0, 2 * DIM * sizeof(float));
    cudaMemsetAsync(s2, 0, 2 * DIM * sizeof(float));
    cudaMemsetAsync(se, 0, 2 * DIM * sizeof(float));
    fill_kernel<<<cdiv(NN * NH, 256), 256>>>(mx, -1e30f, NN * NH);

    const int gN = cdiv(NN, 128), gE = cdiv(NE, 128);

    // Q/K/V in one launch (x-tile L2 reuse across the 3 sibling blocks)
    qkv_gemm<<<dim3(3, gN), 256, SMB_TOTAL>>>(xhi, xlo, wq_h, wq_l, wk_h, wk_l,
                                              wv_h, wv_l, bq, bk, bv, Qh, Kh, Vh);

    // fused Ee GEMM + score/logit/segment-max (A-tile L2 reuse across head halves)
    edge_gemm_fused<<<dim3(2, gE), 256, SMB_TOTAL>>>(eahi, ealo, we_h, we_l, be,
                                                     ei, Aw, Qh, Kh, ethi, etlo, lg, mx);

    // merged denominator + unnormalized scatter
    int eth = NE * NH;
    edge_pass23<<<cdiv(eth, 256), 256>>>(ei, lg, mx, den, Vh, ethi, etlo, wV, rowV);

    node_fix<<<cdiv(NN * 64, 256), 256>>>(wV, rowV, den, VeRow, log_deg, deg_coef, hatth, hattl);

    // h path: WOh + residual(x) -> v1; BN1 -> hbn pair
    mma_gemmB<1, 0, false, false><<<dim3(1, gN), 256, SMB_TOTAL>>>(
        hatth, hattl, woh_h, woh_l, bOh, x, nullptr, nullptr, v1, nullptr, nullptr, nullptr, NN, 128, 128);
    bn_stats<<<1024, 128>>>(v1, NN, s1);
    bn_apply<true><<<cdiv((long long)NN * 64, 256), 256>>>(v1, nullptr, hbnh, hbnl, NN, s1, g1h, b1h, 1.f / NN);

    // e path: WOe + residual(edge_attr) -> eout with FUSED bn stats; then BN apply
    mma_gemmB<1, 0, false, true><<<dim3(1, gE), 256, SMB_TOTAL>>>(
        ethi, etlo, woe_h, woe_l, bOe, edge_attr, nullptr, nullptr, eout, nullptr, nullptr, se, NE, 128, 128);
    bn_apply<false><<<cdiv((long long)NE * 64, 256), 256>>>(eout, eout, nullptr, nullptr, NE, se, g1e, b1e, 1.f / NE);

    // FFN: W1(relu) -> h2a pair; W2 + residual(hbn pair) -> v2; BN2 -> hout
    mma_gemmB<0, 1, true, false><<<dim3(2, gN), 256, SMB_TOTAL>>>(
        hbnh, hbnl, w1_h, w1_l, b1, nullptr, nullptr, nullptr, nullptr, h2ah, h2al, nullptr, NN, 256, 128);
    mma_gemmB<2, 0, false, false><<<dim3(1, gN), 256, SMB_TOTAL>>>(
        h2ah, h2al, w2_h, w2_l, b2, nullptr, hbnh, hbnl, v2, nullptr, nullptr, nullptr, NN, 128, 256);
    bn_stats<<<1024, 128>>>(v2, NN, s2);
    bn_apply<false><<<cdiv((long long)NN * 64, 256), 256>>>(v2, hout, nullptr, nullptr, NN, s2, g2h, b2h, 1.f / NN);
}